// round 1
// baseline (speedup 1.0000x reference)
#include <cuda_runtime.h>
#include <cuda_bf16.h>

// ---------------- problem constants ----------------
#define B      512
#define C1     64
#define C2     128
#define OH1    24          // 28-5+1
#define P1     12
#define OH2    8           // 12-5+1
#define P2     4
#define FLAT   2048        // 128*4*4
#define F1     512
#define F2     10
#define BN_EPS 1e-5f

// ---------------- device scratch (static, no allocations) ----------------
__device__ unsigned g_maxabs[4];
__device__ float g_qw1[C1 * 25];            // ternary conv1 weights
__device__ float g_qw2[C2 * C1 * 25];       // ternary conv2 weights
__device__ float g_qf1[F1 * FLAT];          // ternary fc1 weights
__device__ float g_qf2[F2 * F1];            // ternary fc2 weights
__device__ float g_conv1[B * C1 * OH1 * OH1];   // 75.5 MB
__device__ float g_p1sum[C1 * B], g_p1sq[C1 * B];
__device__ float g_scale1[C1], g_shift1[C1];
__device__ float g_pool1[B * C1 * P1 * P1];     // 18.9 MB
__device__ float g_conv2[B * C2 * OH2 * OH2];   // 16.8 MB
__device__ float g_p2sum[C2 * B], g_p2sq[C2 * B];
__device__ float g_scale2[C2], g_shift2[C2];
__device__ float g_h1[B * FLAT];                // pooled+flattened, 4 MB
__device__ float g_fc1[B * F1];                 // 1 MB
__device__ float g_scale3[F1], g_shift3[F1];

// ---------------- ternary quantization ----------------
__global__ void k_zero_max() {
    if (threadIdx.x < 4) g_maxabs[threadIdx.x] = 0u;
}

__global__ void k_absmax(const float* __restrict__ w, int n, int slot) {
    unsigned m = 0u;
    for (int i = blockIdx.x * blockDim.x + threadIdx.x; i < n; i += gridDim.x * blockDim.x)
        m = max(m, __float_as_uint(fabsf(w[i])));
    #pragma unroll
    for (int o = 16; o; o >>= 1)
        m = max(m, __shfl_xor_sync(0xffffffffu, m, o));
    if ((threadIdx.x & 31) == 0) atomicMax(&g_maxabs[slot], m);
}

__global__ void k_quant(const float* __restrict__ w, int n, int slot) {
    float t = 0.05f * __uint_as_float(g_maxabs[slot]);
    float* dst = (slot == 0) ? g_qw1 : (slot == 1) ? g_qw2 : (slot == 2) ? g_qf1 : g_qf2;
    for (int i = blockIdx.x * blockDim.x + threadIdx.x; i < n; i += gridDim.x * blockDim.x) {
        float v = w[i];
        dst[i] = (v > t) ? 1.0f : ((v < -t) ? -1.0f : 0.0f);
    }
}

// ---------------- conv1: 1->64 ch, 5x5, 28x28 -> 24x24, + BN partials ----------------
// grid (512, 16): block handles 1 image x 4 output channels; 576 threads = one per pixel
__global__ __launch_bounds__(576) void k_conv1(const float* __restrict__ x) {
    __shared__ float sx[784];
    __shared__ float sw[100];
    __shared__ float sred[2][4][18];
    const int b = blockIdx.x, oc0 = blockIdx.y * 4, t = threadIdx.x;

    for (int i = t; i < 784; i += 576) sx[i] = x[b * 784 + i];
    if (t < 100) sw[t] = g_qw1[oc0 * 25 + t];
    __syncthreads();

    const int oy = t / 24, ox = t % 24;
    float acc[4] = {0.f, 0.f, 0.f, 0.f};
    #pragma unroll
    for (int kh = 0; kh < 5; kh++) {
        #pragma unroll
        for (int kw = 0; kw < 5; kw++) {
            float xv = sx[(oy + kh) * 28 + ox + kw];
            #pragma unroll
            for (int j = 0; j < 4; j++)
                acc[j] = fmaf(sw[j * 25 + kh * 5 + kw], xv, acc[j]);
        }
    }

    const int wid = t >> 5, lane = t & 31;
    #pragma unroll
    for (int j = 0; j < 4; j++) {
        g_conv1[(b * C1 + oc0 + j) * 576 + t] = acc[j];
        float s = acc[j], q = acc[j] * acc[j];
        #pragma unroll
        for (int o = 16; o; o >>= 1) {
            s += __shfl_xor_sync(0xffffffffu, s, o);
            q += __shfl_xor_sync(0xffffffffu, q, o);
        }
        if (lane == 0) { sred[0][j][wid] = s; sred[1][j][wid] = q; }
    }
    __syncthreads();
    if (t < 4) {
        float s = 0.f, q = 0.f;
        for (int w = 0; w < 18; w++) { s += sred[0][t][w]; q += sred[1][t][w]; }
        g_p1sum[(oc0 + t) * B + b] = s;
        g_p1sq [(oc0 + t) * B + b] = q;
    }
}

// ---------------- BN finalize (deterministic tree over 512 partials) ----------------
__global__ void k_bnfin1(const float* __restrict__ gamma, const float* __restrict__ beta) {
    __shared__ float s1[512], s2[512];
    const int c = blockIdx.x, t = threadIdx.x;
    s1[t] = g_p1sum[c * B + t];
    s2[t] = g_p1sq [c * B + t];
    __syncthreads();
    for (int s = 256; s > 0; s >>= 1) {
        if (t < s) { s1[t] += s1[t + s]; s2[t] += s2[t + s]; }
        __syncthreads();
    }
    if (t == 0) {
        const float invN = 1.0f / (float)(B * 576);
        float mean = s1[0] * invN;
        float var  = s2[0] * invN - mean * mean;
        float sc = gamma[c] * rsqrtf(var + BN_EPS);
        g_scale1[c] = sc;
        g_shift1[c] = beta[c] - mean * sc;
    }
}

__global__ void k_bnfin2(const float* __restrict__ gamma, const float* __restrict__ beta) {
    __shared__ float s1[512], s2[512];
    const int c = blockIdx.x, t = threadIdx.x;
    s1[t] = g_p2sum[c * B + t];
    s2[t] = g_p2sq [c * B + t];
    __syncthreads();
    for (int s = 256; s > 0; s >>= 1) {
        if (t < s) { s1[t] += s1[t + s]; s2[t] += s2[t + s]; }
        __syncthreads();
    }
    if (t == 0) {
        const float invN = 1.0f / (float)(B * 64);
        float mean = s1[0] * invN;
        float var  = s2[0] * invN - mean * mean;
        float sc = gamma[c] * rsqrtf(var + BN_EPS);
        g_scale2[c] = sc;
        g_shift2[c] = beta[c] - mean * sc;
    }
}

// ---------------- bn1 + relu + maxpool2 : conv1_out -> pool1 ----------------
__global__ void k_pool1() {
    int idx = blockIdx.x * blockDim.x + threadIdx.x;
    if (idx >= B * C1 * P1 * P1) return;
    int px = idx % P1, py = (idx / P1) % P1, c = (idx / (P1 * P1)) % C1, b = idx / (P1 * P1 * C1);
    const float* src = g_conv1 + (b * C1 + c) * 576 + (py * 2) * 24 + px * 2;
    float sc = g_scale1[c], sh = g_shift1[c];
    float a0 = fmaf(sc, src[0], sh);
    float a1 = fmaf(sc, src[1], sh);
    float a2 = fmaf(sc, src[24], sh);
    float a3 = fmaf(sc, src[25], sh);
    float m = fmaxf(fmaxf(a0, a1), fmaxf(a2, a3));
    g_pool1[idx] = fmaxf(m, 0.0f);
}

// ---------------- conv2: 64->128 ch, 5x5, 12x12 -> 8x8, + BN partials ----------------
// grid (512, 2), 256 threads. Block: one image x 64 out-channels (all 64 pixels).
// Thread: 4 oc x 4 px register tile. Input image (64x12x12) + weight ci-chunks in smem.
#define CONV2_SMEM_FLOATS (9216 + 12800)
__global__ __launch_bounds__(256) void k_conv2() {
    extern __shared__ float sm[];
    float* sx = sm;               // 64*144 = 9216 floats
    float* sw = sm + 9216;        // 64 oc * 8 ci * 25 = 12800 floats
    const int b = blockIdx.x, ocb = blockIdx.y * 64, t = threadIdx.x;

    for (int i = t; i < 9216; i += 256) sx[i] = g_pool1[b * 9216 + i];

    const int pxg = t & 15, ocg = t >> 4;          // 16 px-groups x 16 oc-groups
    const int py = pxg >> 1, px0 = (pxg & 1) * 4;  // 4 px of this thread share a row
    float acc[4][4];
    #pragma unroll
    for (int j = 0; j < 4; j++)
        #pragma unroll
        for (int i = 0; i < 4; i++) acc[j][i] = 0.f;

    for (int cc = 0; cc < 64; cc += 8) {
        __syncthreads();
        for (int i = t; i < 12800; i += 256) {
            int oc_l = i / 200, r = i % 200;
            sw[i] = g_qw2[((ocb + oc_l) * C1 + cc + r / 25) * 25 + (r % 25)];
        }
        __syncthreads();
        #pragma unroll 1
        for (int ci = 0; ci < 8; ci++) {
            const float* xb = sx + (cc + ci) * 144 + py * 12 + px0;
            const float* wb = sw + ocg * 4 * 200 + ci * 25;
            #pragma unroll
            for (int kh = 0; kh < 5; kh++) {
                float xv[8];
                #pragma unroll
                for (int j = 0; j < 8; j++) xv[j] = xb[kh * 12 + j];
                #pragma unroll
                for (int kw = 0; kw < 5; kw++) {
                    #pragma unroll
                    for (int jo = 0; jo < 4; jo++) {
                        float w = wb[jo * 200 + kh * 5 + kw];
                        #pragma unroll
                        for (int i2 = 0; i2 < 4; i2++)
                            acc[jo][i2] = fmaf(w, xv[kw + i2], acc[jo][i2]);
                    }
                }
            }
        }
    }

    #pragma unroll
    for (int jo = 0; jo < 4; jo++) {
        int oc = ocb + ocg * 4 + jo;
        #pragma unroll
        for (int i2 = 0; i2 < 4; i2++)
            g_conv2[(b * C2 + oc) * 64 + pxg * 4 + i2] = acc[jo][i2];
    }

    // per-(oc, image) BN partials — deterministic fixed-order staging + reduce
    __syncthreads();
    float* sr  = sx;          // 64*16
    float* sr2 = sx + 1024;   // 64*16
    #pragma unroll
    for (int jo = 0; jo < 4; jo++) {
        float s = acc[jo][0] + acc[jo][1] + acc[jo][2] + acc[jo][3];
        float q = acc[jo][0]*acc[jo][0] + acc[jo][1]*acc[jo][1]
                + acc[jo][2]*acc[jo][2] + acc[jo][3]*acc[jo][3];
        sr [(ocg * 4 + jo) * 16 + pxg] = s;
        sr2[(ocg * 4 + jo) * 16 + pxg] = q;
    }
    __syncthreads();
    if (t < 64) {
        float s = 0.f, q = 0.f;
        for (int g = 0; g < 16; g++) { s += sr[t * 16 + g]; q += sr2[t * 16 + g]; }
        g_p2sum[(ocb + t) * B + b] = s;
        g_p2sq [(ocb + t) * B + b] = q;
    }
}

// ---------------- bn2 + relu + maxpool2 -> flattened h1 ----------------
__global__ void k_pool2() {
    int idx = blockIdx.x * blockDim.x + threadIdx.x;
    if (idx >= B * C2 * P2 * P2) return;
    int px = idx % P2, py = (idx / P2) % P2, c = (idx / (P2 * P2)) % C2, b = idx / (P2 * P2 * C2);
    const float* src = g_conv2 + (b * C2 + c) * 64 + (py * 2) * 8 + px * 2;
    float sc = g_scale2[c], sh = g_shift2[c];
    float a0 = fmaf(sc, src[0], sh);
    float a1 = fmaf(sc, src[1], sh);
    float a2 = fmaf(sc, src[8], sh);
    float a3 = fmaf(sc, src[9], sh);
    float m = fmaxf(fmaxf(a0, a1), fmaxf(a2, a3));
    g_h1[b * FLAT + c * 16 + py * 4 + px] = fmaxf(m, 0.0f);
}

// ---------------- fc1: [512,2048] x [512,2048]^T -> [512,512] ----------------
// grid (8, 16): 64-row x 32-col tiles; 256 threads; 4x2 register tile.
__global__ __launch_bounds__(256) void k_fc1() {
    __shared__ float sA[16][64];
    __shared__ float sB[16][32];
    const int t = threadIdx.x, bi = blockIdx.x, fi = blockIdx.y;
    const int tr = t & 15, tc = t >> 4;
    float acc[4][2];
    #pragma unroll
    for (int i = 0; i < 4; i++) { acc[i][0] = 0.f; acc[i][1] = 0.f; }

    for (int k0 = 0; k0 < FLAT; k0 += 16) {
        __syncthreads();
        {
            int row = t >> 2, kb = (t & 3) * 4;
            float4 a = *(const float4*)&g_h1[(bi * 64 + row) * FLAT + k0 + kb];
            sA[kb + 0][row] = a.x; sA[kb + 1][row] = a.y;
            sA[kb + 2][row] = a.z; sA[kb + 3][row] = a.w;
        }
        {
            int row = t >> 3, kb = (t & 7) * 2;
            float2 v = *(const float2*)&g_qf1[(fi * 32 + row) * FLAT + k0 + kb];
            sB[kb + 0][row] = v.x; sB[kb + 1][row] = v.y;
        }
        __syncthreads();
        #pragma unroll
        for (int kk = 0; kk < 16; kk++) {
            float4 av = *(const float4*)&sA[kk][tr * 4];
            float2 bv = *(const float2*)&sB[kk][tc * 2];
            acc[0][0] = fmaf(av.x, bv.x, acc[0][0]); acc[0][1] = fmaf(av.x, bv.y, acc[0][1]);
            acc[1][0] = fmaf(av.y, bv.x, acc[1][0]); acc[1][1] = fmaf(av.y, bv.y, acc[1][1]);
            acc[2][0] = fmaf(av.z, bv.x, acc[2][0]); acc[2][1] = fmaf(av.z, bv.y, acc[2][1]);
            acc[3][0] = fmaf(av.w, bv.x, acc[3][0]); acc[3][1] = fmaf(av.w, bv.y, acc[3][1]);
        }
    }
    #pragma unroll
    for (int i = 0; i < 4; i++)
        #pragma unroll
        for (int j = 0; j < 2; j++)
            g_fc1[(bi * 64 + tr * 4 + i) * F1 + fi * 32 + tc * 2 + j] = acc[i][j];
}

// ---------------- bn3 stats over batch + finalize ----------------
// grid 16 blocks x 256 threads; each block owns 32 features.
__global__ void k_bnstats3(const float* __restrict__ gamma, const float* __restrict__ beta) {
    __shared__ float ss[256], sq[256];
    const int t = threadIdx.x;
    const int f = blockIdx.x * 32 + (t & 31);
    const int bo = t >> 5;
    float s = 0.f, q = 0.f;
    for (int b = bo; b < B; b += 8) {
        float v = g_fc1[b * F1 + f];
        s += v; q += v * v;
    }
    ss[t] = s; sq[t] = q;
    __syncthreads();
    if (t < 32) {
        float S = 0.f, Q = 0.f;
        for (int w = 0; w < 8; w++) { S += ss[w * 32 + t]; Q += sq[w * 32 + t]; }
        const float invN = 1.0f / (float)B;
        float mean = S * invN;
        float var  = Q * invN - mean * mean;
        int fg = blockIdx.x * 32 + t;
        float sc = gamma[fg] * rsqrtf(var + BN_EPS);
        g_scale3[fg] = sc;
        g_shift3[fg] = beta[fg] - mean * sc;
    }
}

// ---------------- bn3 + relu + fc2 -> output ----------------
// grid 512 (one batch row), 320 threads (10 warps, one warp per output class)
__global__ void k_fc2(const float* __restrict__ fc2_b, float* __restrict__ out) {
    __shared__ float sh[F1];
    const int b = blockIdx.x, t = threadIdx.x;
    for (int i = t; i < F1; i += 320) {
        float v = g_fc1[b * F1 + i];
        sh[i] = fmaxf(fmaf(g_scale3[i], v, g_shift3[i]), 0.0f);
    }
    __syncthreads();
    const int w = t >> 5, lane = t & 31;
    float acc = 0.f;
    for (int f = lane; f < F1; f += 32)
        acc = fmaf(sh[f], g_qf2[w * F1 + f], acc);
    #pragma unroll
    for (int o = 16; o; o >>= 1)
        acc += __shfl_xor_sync(0xffffffffu, acc, o);
    if (lane == 0) out[b * F2 + w] = acc + fc2_b[w];
}

// ---------------- launcher ----------------
extern "C" void kernel_launch(void* const* d_in, const int* in_sizes, int n_in,
                              void* d_out, int out_size) {
    const float* x       = (const float*)d_in[0];
    const float* conv1_w = (const float*)d_in[1];
    const float* bn1_g   = (const float*)d_in[3];
    const float* bn1_b   = (const float*)d_in[4];
    const float* conv2_w = (const float*)d_in[5];
    const float* bn2_g   = (const float*)d_in[7];
    const float* bn2_b   = (const float*)d_in[8];
    const float* fc1_w   = (const float*)d_in[9];
    const float* bn3_g   = (const float*)d_in[11];
    const float* bn3_b   = (const float*)d_in[12];
    const float* fc2_w   = (const float*)d_in[13];
    const float* fc2_b   = (const float*)d_in[14];
    float* out = (float*)d_out;

    cudaFuncSetAttribute(k_conv2, cudaFuncAttributeMaxDynamicSharedMemorySize,
                         CONV2_SMEM_FLOATS * (int)sizeof(float));

    // ternary thresholds + quantization (biases dropped: BN train-mode cancels them)
    k_zero_max<<<1, 32>>>();
    k_absmax<<<8, 256>>>(conv1_w, C1 * 25, 0);
    k_absmax<<<256, 256>>>(conv2_w, C2 * C1 * 25, 1);
    k_absmax<<<1024, 256>>>(fc1_w, F1 * FLAT, 2);
    k_absmax<<<20, 256>>>(fc2_w, F2 * F1, 3);
    k_quant<<<8, 256>>>(conv1_w, C1 * 25, 0);
    k_quant<<<256, 256>>>(conv2_w, C2 * C1 * 25, 1);
    k_quant<<<1024, 256>>>(fc1_w, F1 * FLAT, 2);
    k_quant<<<20, 256>>>(fc2_w, F2 * F1, 3);

    // stage 1
    k_conv1<<<dim3(B, C1 / 4), 576>>>(x);
    k_bnfin1<<<C1, 512>>>(bn1_g, bn1_b);
    k_pool1<<<(B * C1 * P1 * P1 + 255) / 256, 256>>>();

    // stage 2
    k_conv2<<<dim3(B, 2), 256, CONV2_SMEM_FLOATS * (int)sizeof(float)>>>();
    k_bnfin2<<<C2, 512>>>(bn2_g, bn2_b);
    k_pool2<<<(B * C2 * P2 * P2 + 255) / 256, 256>>>();

    // stage 3
    k_fc1<<<dim3(8, 16), 256>>>();
    k_bnstats3<<<16, 256>>>(bn3_g, bn3_b);
    k_fc2<<<B, 320>>>(fc2_b, out);
}

// round 2
// speedup vs baseline: 2.7322x; 2.7322x over previous
#include <cuda_runtime.h>
#include <cuda_bf16.h>

// ---------------- problem constants ----------------
#define B      512
#define C1     64
#define C2     128
#define P1     12
#define FLAT   2048
#define F1     512
#define F2     10
#define BN_EPS 1e-5f

// ---------------- device scratch ----------------
__device__ unsigned g_maxabs[4];
__device__ float g_qw1[C1 * 25];                 // conv1 ternary [oc][25]
__device__ float g_qw2[25 * C2 * C1];            // conv2 ternary [khkw][oc][ci]
__device__ float g_qf1[F1 * FLAT];               // fc1 ternary [f][k]
__device__ float g_qf2[F2 * F1];
__device__ float g_pool1[B * C1 * P1 * P1];      // RAW pooled conv1 (pre-BN)
__device__ float g_p1sum[C1 * B], g_p1sq[C1 * B];
__device__ float g_scale1[C1], g_shift1[C1];
__device__ float g_p2sum[C2 * B], g_p2sq[C2 * B];
__device__ float g_scale2[C2], g_shift2[C2];
__device__ float g_h1[B * FLAT];                 // RAW pooled conv2 (pre-BN), [b][c*16+y*4+x]
__device__ float g_fc1[B * F1];                  // RAW fc1 (pre-BN)
__device__ float g_scale3[F1], g_shift3[F1];

// ---------------- quantization (3 launches total) ----------------
__global__ void k_zero_max() {
    if (threadIdx.x < 4) g_maxabs[threadIdx.x] = 0u;
}

__global__ void k_absmax_all(const float* __restrict__ w0, const float* __restrict__ w1,
                             const float* __restrict__ w2, const float* __restrict__ w3) {
    const int slot = blockIdx.y;
    const float* w = (slot == 0) ? w0 : (slot == 1) ? w1 : (slot == 2) ? w2 : w3;
    const int n = (slot == 0) ? 1600 : (slot == 1) ? 204800 : (slot == 2) ? 1048576 : 5120;
    unsigned m = 0u;
    for (int i = blockIdx.x * blockDim.x + threadIdx.x; i < n; i += gridDim.x * blockDim.x)
        m = max(m, __float_as_uint(fabsf(w[i])));
    #pragma unroll
    for (int o = 16; o; o >>= 1)
        m = max(m, __shfl_xor_sync(0xffffffffu, m, o));
    if ((threadIdx.x & 31) == 0) atomicMax(&g_maxabs[slot], m);
}

__global__ void k_quant_all(const float* __restrict__ w0, const float* __restrict__ w1,
                            const float* __restrict__ w2, const float* __restrict__ w3) {
    const int slot = blockIdx.y;
    const float* w = (slot == 0) ? w0 : (slot == 1) ? w1 : (slot == 2) ? w2 : w3;
    const int n = (slot == 0) ? 1600 : (slot == 1) ? 204800 : (slot == 2) ? 1048576 : 5120;
    const float t = 0.05f * __uint_as_float(g_maxabs[slot]);
    for (int i = blockIdx.x * blockDim.x + threadIdx.x; i < n; i += gridDim.x * blockDim.x) {
        float v = w[i];
        float q = (v > t) ? 1.0f : ((v < -t) ? -1.0f : 0.0f);
        if (slot == 0)      g_qw1[i] = q;
        else if (slot == 1) {
            int oc = i / 1600, rem = i % 1600, ci = rem / 25, kk = rem % 25;
            g_qw2[kk * (C2 * C1) + oc * C1 + ci] = q;   // [khkw][oc][ci]
        }
        else if (slot == 2) g_qf1[i] = q;
        else                g_qf2[i] = q;
    }
}

// ---------------- conv1 (scalar) + fused raw max-pool + BN1 partials ----------------
// grid (512, 16), 576 threads: 1 image x 4 oc, 1 thread per conv output pixel
__global__ __launch_bounds__(576) void k_conv1(const float* __restrict__ x) {
    __shared__ float sx[784];
    __shared__ float sw[100];
    __shared__ float sred[2][4][18];
    __shared__ float sconv[4][576];
    const int b = blockIdx.x, oc0 = blockIdx.y * 4, t = threadIdx.x;

    for (int i = t; i < 784; i += 576) sx[i] = x[b * 784 + i];
    if (t < 100) sw[t] = g_qw1[oc0 * 25 + t];
    __syncthreads();

    const int oy = t / 24, ox = t % 24;
    float acc[4] = {0.f, 0.f, 0.f, 0.f};
    #pragma unroll
    for (int kh = 0; kh < 5; kh++) {
        #pragma unroll
        for (int kw = 0; kw < 5; kw++) {
            float xv = sx[(oy + kh) * 28 + ox + kw];
            #pragma unroll
            for (int j = 0; j < 4; j++)
                acc[j] = fmaf(sw[j * 25 + kh * 5 + kw], xv, acc[j]);
        }
    }

    const int wid = t >> 5, lane = t & 31;
    #pragma unroll
    for (int j = 0; j < 4; j++) {
        sconv[j][t] = acc[j];
        float s = acc[j], q = acc[j] * acc[j];
        #pragma unroll
        for (int o = 16; o; o >>= 1) {
            s += __shfl_xor_sync(0xffffffffu, s, o);
            q += __shfl_xor_sync(0xffffffffu, q, o);
        }
        if (lane == 0) { sred[0][j][wid] = s; sred[1][j][wid] = q; }
    }
    __syncthreads();
    if (t < 144) {
        const int py = t / 12, px = t % 12;
        const int base = (2 * py) * 24 + 2 * px;
        #pragma unroll
        for (int j = 0; j < 4; j++) {
            float m = fmaxf(fmaxf(sconv[j][base], sconv[j][base + 1]),
                            fmaxf(sconv[j][base + 24], sconv[j][base + 25]));
            g_pool1[(b * C1 + oc0 + j) * 144 + t] = m;   // RAW pooled
        }
    }
    if (t < 4) {
        float s = 0.f, q = 0.f;
        for (int w = 0; w < 18; w++) { s += sred[0][t][w]; q += sred[1][t][w]; }
        g_p1sum[(oc0 + t) * B + b] = s;
        g_p1sq [(oc0 + t) * B + b] = q;
    }
}

// ---------------- BN finalize ----------------
__global__ void k_bnfin1(const float* __restrict__ gamma, const float* __restrict__ beta) {
    __shared__ float s1[512], s2[512];
    const int c = blockIdx.x, t = threadIdx.x;
    s1[t] = g_p1sum[c * B + t];
    s2[t] = g_p1sq [c * B + t];
    __syncthreads();
    for (int s = 256; s > 0; s >>= 1) {
        if (t < s) { s1[t] += s1[t + s]; s2[t] += s2[t + s]; }
        __syncthreads();
    }
    if (t == 0) {
        const float invN = 1.0f / (float)(B * 576);
        float mean = s1[0] * invN;
        float var  = s2[0] * invN - mean * mean;
        float sc = gamma[c] * rsqrtf(var + BN_EPS);
        g_scale1[c] = sc;
        g_shift1[c] = beta[c] - mean * sc;
    }
}

__global__ void k_bnfin2(const float* __restrict__ gamma, const float* __restrict__ beta) {
    __shared__ float s1[512], s2[512];
    const int c = blockIdx.x, t = threadIdx.x;
    s1[t] = g_p2sum[c * B + t];
    s2[t] = g_p2sq [c * B + t];
    __syncthreads();
    for (int s = 256; s > 0; s >>= 1) {
        if (t < s) { s1[t] += s1[t + s]; s2[t] += s2[t + s]; }
        __syncthreads();
    }
    if (t == 0) {
        const float invN = 1.0f / (float)(B * 64);
        float mean = s1[0] * invN;
        float var  = s2[0] * invN - mean * mean;
        float sc = gamma[c] * rsqrtf(var + BN_EPS);
        g_scale2[c] = sc;
        g_shift2[c] = beta[c] - mean * sc;
    }
}

// ---------------- conv2: tf32 mma implicit GEMM, 2 images/block ----------------
// GEMM: [128 oc x 1600] x [1600 x 128 px(2 imgs)]; K = (kh*5+kw)*64 + ci, chunks of 32.
// 256 threads = 8 warps arranged 2(M) x 4(N); warp tile 64x32.
#define CV2_SA_OFF 18432
#define CV2_SB_OFF (18432 + 4608)
#define CV2_SMEM_FLOATS (18432 + 4608 + 4352)
#define CV2_SMEM_BYTES (CV2_SMEM_FLOATS * 4)

__global__ __launch_bounds__(256) void k_conv2() {
    extern __shared__ float sm[];
    float* sx = sm;                         // 2 x 64ci x 144, tf32 bits, BN1+ReLU applied
    float* sA = sm + CV2_SA_OFF;            // 128 oc x 32 k, stride 36
    float* sB = sm + CV2_SB_OFF;            // 32 k x 128 px, stride 136
    const int b2 = blockIdx.x * 2;
    const int t = threadIdx.x;
    const int lane = t & 31, warp = t >> 5;
    const int l4 = lane >> 2, lm4 = lane & 3;
    const int wm = warp >> 2, wn = warp & 3;
    const int m0w = wm * 64, n0w = wn * 32;

    // load both images: BN1 affine + ReLU + tf32 round
    for (int i = t; i < 18432; i += 256) {
        float v = g_pool1[b2 * 9216 + i];
        int ci = (i % 9216) / 144;
        v = fmaxf(fmaf(g_scale1[ci], v, g_shift1[ci]), 0.0f);
        unsigned u; asm("cvt.rna.tf32.f32 %0, %1;" : "=r"(u) : "f"(v));
        sx[i] = __uint_as_float(u);
    }

    float c[4][4][4];
    #pragma unroll
    for (int i = 0; i < 4; i++)
        #pragma unroll
        for (int j = 0; j < 4; j++)
            #pragma unroll
            for (int r = 0; r < 4; r++) c[i][j][r] = 0.f;
    __syncthreads();

    // staging thread mapping for sB
    const int pxt = t & 127;
    const int imgt = pxt >> 6, pt = pxt & 63;
    const int yt = pt >> 3, xt = pt & 7;
    const int cih = (t >> 7) * 16;          // ci_local base (0 or 16)

    for (int ch = 0; ch < 50; ch++) {
        const int khkw = ch >> 1, ci0 = (ch & 1) * 32;
        const int kh = khkw / 5, kw = khkw % 5;
        if (ch) __syncthreads();
        // stage weights [oc][ci0..ci0+31]
        const float* wsrc = g_qw2 + khkw * (C2 * C1) + ci0;
        #pragma unroll
        for (int j = 0; j < 16; j++) {
            int idx = t + 256 * j;
            int oc = idx >> 5, cl = idx & 31;
            sA[oc * 36 + cl] = wsrc[oc * 64 + cl];
        }
        // stage im2col chunk: sB[ci_l][px] = sx[img][ci0+ci_l][(y+kh)*12 + x+kw]
        {
            const float* xb = sx + imgt * 9216 + (ci0 + cih) * 144 + (yt + kh) * 12 + xt + kw;
            float* bb = sB + cih * 136 + pxt;
            #pragma unroll
            for (int j = 0; j < 16; j++)
                bb[j * 136] = xb[j * 144];
        }
        __syncthreads();
        #pragma unroll
        for (int ks = 0; ks < 4; ks++) {
            const int k0 = ks * 8;
            unsigned a[4][4], bf[4][2];
            #pragma unroll
            for (int mt = 0; mt < 4; mt++) {
                const float* ap = sA + (m0w + mt * 16 + l4) * 36 + k0 + lm4;
                a[mt][0] = __float_as_uint(ap[0]);
                a[mt][1] = __float_as_uint(ap[8 * 36]);
                a[mt][2] = __float_as_uint(ap[4]);
                a[mt][3] = __float_as_uint(ap[8 * 36 + 4]);
            }
            #pragma unroll
            for (int nt = 0; nt < 4; nt++) {
                const float* bp = sB + (k0 + lm4) * 136 + n0w + nt * 8 + l4;
                bf[nt][0] = __float_as_uint(bp[0]);
                bf[nt][1] = __float_as_uint(bp[4 * 136]);
            }
            #pragma unroll
            for (int mt = 0; mt < 4; mt++)
                #pragma unroll
                for (int nt = 0; nt < 4; nt++)
                    asm volatile(
                        "mma.sync.aligned.m16n8k8.row.col.f32.tf32.tf32.f32 "
                        "{%0,%1,%2,%3},{%4,%5,%6,%7},{%8,%9},{%0,%1,%2,%3};"
                        : "+f"(c[mt][nt][0]), "+f"(c[mt][nt][1]),
                          "+f"(c[mt][nt][2]), "+f"(c[mt][nt][3])
                        : "r"(a[mt][0]), "r"(a[mt][1]), "r"(a[mt][2]), "r"(a[mt][3]),
                          "r"(bf[nt][0]), "r"(bf[nt][1]));
        }
    }

    // ---- epilogue: raw 2x2 max-pool (thread-local!) + BN2 partial sums ----
    const int img = wn >> 1, yb = (wn & 1) * 2;
    #pragma unroll
    for (int mt = 0; mt < 4; mt++) {
        int rA = m0w + mt * 16 + l4;
        #pragma unroll
        for (int ntp = 0; ntp < 2; ntp++) {
            float pA = fmaxf(fmaxf(c[mt][2*ntp][0], c[mt][2*ntp][1]),
                             fmaxf(c[mt][2*ntp+1][0], c[mt][2*ntp+1][1]));
            float pB = fmaxf(fmaxf(c[mt][2*ntp][2], c[mt][2*ntp][3]),
                             fmaxf(c[mt][2*ntp+1][2], c[mt][2*ntp+1][3]));
            int yy = yb + ntp;
            g_h1[(b2 + img) * FLAT + rA * 16 + yy * 4 + lm4] = pA;
            g_h1[(b2 + img) * FLAT + (rA + 8) * 16 + yy * 4 + lm4] = pB;
        }
    }
    float* srs = sm;          // reuse sx region (no longer read)
    float* srq = sm + 1024;
    #pragma unroll
    for (int mt = 0; mt < 4; mt++) {
        float s0 = 0.f, q0 = 0.f, s1 = 0.f, q1 = 0.f;
        #pragma unroll
        for (int nt = 0; nt < 4; nt++) {
            s0 += c[mt][nt][0] + c[mt][nt][1];
            q0 += c[mt][nt][0]*c[mt][nt][0] + c[mt][nt][1]*c[mt][nt][1];
            s1 += c[mt][nt][2] + c[mt][nt][3];
            q1 += c[mt][nt][2]*c[mt][nt][2] + c[mt][nt][3]*c[mt][nt][3];
        }
        s0 += __shfl_xor_sync(0xffffffffu, s0, 1); s0 += __shfl_xor_sync(0xffffffffu, s0, 2);
        q0 += __shfl_xor_sync(0xffffffffu, q0, 1); q0 += __shfl_xor_sync(0xffffffffu, q0, 2);
        s1 += __shfl_xor_sync(0xffffffffu, s1, 1); s1 += __shfl_xor_sync(0xffffffffu, s1, 2);
        q1 += __shfl_xor_sync(0xffffffffu, q1, 1); q1 += __shfl_xor_sync(0xffffffffu, q1, 2);
        if (lm4 == 0) {
            int rA = m0w + mt * 16 + l4;
            srs[(rA * 2 + img) * 2 + (wn & 1)] = s0;
            srq[(rA * 2 + img) * 2 + (wn & 1)] = q0;
            srs[((rA + 8) * 2 + img) * 2 + (wn & 1)] = s1;
            srq[((rA + 8) * 2 + img) * 2 + (wn & 1)] = q1;
        }
    }
    __syncthreads();
    {
        int oc = t & 127, im = t >> 7;
        float s = srs[(oc * 2 + im) * 2] + srs[(oc * 2 + im) * 2 + 1];
        float q = srq[(oc * 2 + im) * 2] + srq[(oc * 2 + im) * 2 + 1];
        g_p2sum[oc * B + b2 + im] = s;
        g_p2sq [oc * B + b2 + im] = q;
    }
}

// ---------------- fc1: tf32 mma GEMM [512,2048]x[512,2048]^T, BN2+ReLU fused in A-load --
// grid (8 b-tiles, 8 f-tiles), 128 threads = 4 warps (2x2), warp tile 32x32
__global__ __launch_bounds__(128) void k_fc1() {
    __shared__ float sA[64 * 36];       // [b_l][k_l] pad 36
    __shared__ float sB[32 * 73];       // [k_l][f_l] pad 73
    const int t = threadIdx.x;
    const int lane = t & 31, warp = t >> 5;
    const int l4 = lane >> 2, lm4 = lane & 3;
    const int wm = warp >> 1, wn = warp & 1;
    const int b0 = blockIdx.x * 64, f0 = blockIdx.y * 64;
    const int m0w = wm * 32, n0w = wn * 32;

    float c[2][4][4];
    #pragma unroll
    for (int i = 0; i < 2; i++)
        #pragma unroll
        for (int j = 0; j < 4; j++)
            #pragma unroll
            for (int r = 0; r < 4; r++) c[i][j][r] = 0.f;

    for (int kc = 0; kc < 64; kc++) {
        if (kc) __syncthreads();
        #pragma unroll
        for (int j = 0; j < 16; j++) {
            int idx = t + 128 * j;
            int bl = idx >> 5, kl = idx & 31;
            int kg = kc * 32 + kl, cch = kg >> 4;
            float v = g_h1[(b0 + bl) * FLAT + kg];
            v = fmaxf(fmaf(g_scale2[cch], v, g_shift2[cch]), 0.0f);
            unsigned u; asm("cvt.rna.tf32.f32 %0, %1;" : "=r"(u) : "f"(v));
            sA[bl * 36 + kl] = __uint_as_float(u);
        }
        #pragma unroll
        for (int j = 0; j < 16; j++) {
            int idx = t + 128 * j;
            int fl = idx >> 5, kl = idx & 31;
            sB[kl * 73 + fl] = g_qf1[(f0 + fl) * FLAT + kc * 32 + kl];
        }
        __syncthreads();
        #pragma unroll
        for (int ks = 0; ks < 4; ks++) {
            const int k0 = ks * 8;
            unsigned a[2][4], bf[4][2];
            #pragma unroll
            for (int mt = 0; mt < 2; mt++) {
                const float* ap = sA + (m0w + mt * 16 + l4) * 36 + k0 + lm4;
                a[mt][0] = __float_as_uint(ap[0]);
                a[mt][1] = __float_as_uint(ap[8 * 36]);
                a[mt][2] = __float_as_uint(ap[4]);
                a[mt][3] = __float_as_uint(ap[8 * 36 + 4]);
            }
            #pragma unroll
            for (int nt = 0; nt < 4; nt++) {
                const float* bp = sB + (k0 + lm4) * 73 + n0w + nt * 8 + l4;
                bf[nt][0] = __float_as_uint(bp[0]);
                bf[nt][1] = __float_as_uint(bp[4 * 73]);
            }
            #pragma unroll
            for (int mt = 0; mt < 2; mt++)
                #pragma unroll
                for (int nt = 0; nt < 4; nt++)
                    asm volatile(
                        "mma.sync.aligned.m16n8k8.row.col.f32.tf32.tf32.f32 "
                        "{%0,%1,%2,%3},{%4,%5,%6,%7},{%8,%9},{%0,%1,%2,%3};"
                        : "+f"(c[mt][nt][0]), "+f"(c[mt][nt][1]),
                          "+f"(c[mt][nt][2]), "+f"(c[mt][nt][3])
                        : "r"(a[mt][0]), "r"(a[mt][1]), "r"(a[mt][2]), "r"(a[mt][3]),
                          "r"(bf[nt][0]), "r"(bf[nt][1]));
        }
    }
    #pragma unroll
    for (int mt = 0; mt < 2; mt++) {
        int rA = b0 + m0w + mt * 16 + l4;
        #pragma unroll
        for (int nt = 0; nt < 4; nt++) {
            int cc = f0 + n0w + nt * 8 + 2 * lm4;
            *(float2*)&g_fc1[rA * F1 + cc]       = make_float2(c[mt][nt][0], c[mt][nt][1]);
            *(float2*)&g_fc1[(rA + 8) * F1 + cc] = make_float2(c[mt][nt][2], c[mt][nt][3]);
        }
    }
}

// ---------------- bn3 stats ----------------
__global__ void k_bnstats3(const float* __restrict__ gamma, const float* __restrict__ beta) {
    __shared__ float ss[256], sq[256];
    const int t = threadIdx.x;
    const int f = blockIdx.x * 32 + (t & 31);
    const int bo = t >> 5;
    float s = 0.f, q = 0.f;
    for (int b = bo; b < B; b += 8) {
        float v = g_fc1[b * F1 + f];
        s += v; q += v * v;
    }
    ss[t] = s; sq[t] = q;
    __syncthreads();
    if (t < 32) {
        float S = 0.f, Q = 0.f;
        for (int w = 0; w < 8; w++) { S += ss[w * 32 + t]; Q += sq[w * 32 + t]; }
        const float invN = 1.0f / (float)B;
        float mean = S * invN;
        float var  = Q * invN - mean * mean;
        int fg = blockIdx.x * 32 + t;
        float sc = gamma[fg] * rsqrtf(var + BN_EPS);
        g_scale3[fg] = sc;
        g_shift3[fg] = beta[fg] - mean * sc;
    }
}

// ---------------- bn3 + relu + fc2 ----------------
__global__ void k_fc2(const float* __restrict__ fc2_b, float* __restrict__ out) {
    __shared__ float sh[F1];
    const int b = blockIdx.x, t = threadIdx.x;
    for (int i = t; i < F1; i += 320) {
        float v = g_fc1[b * F1 + i];
        sh[i] = fmaxf(fmaf(g_scale3[i], v, g_shift3[i]), 0.0f);
    }
    __syncthreads();
    const int w = t >> 5, lane = t & 31;
    float acc = 0.f;
    for (int f = lane; f < F1; f += 32)
        acc = fmaf(sh[f], g_qf2[w * F1 + f], acc);
    #pragma unroll
    for (int o = 16; o; o >>= 1)
        acc += __shfl_xor_sync(0xffffffffu, acc, o);
    if (lane == 0) out[b * F2 + w] = acc + fc2_b[w];
}

// ---------------- launcher ----------------
extern "C" void kernel_launch(void* const* d_in, const int* in_sizes, int n_in,
                              void* d_out, int out_size) {
    const float* x       = (const float*)d_in[0];
    const float* conv1_w = (const float*)d_in[1];
    const float* bn1_g   = (const float*)d_in[3];
    const float* bn1_b   = (const float*)d_in[4];
    const float* conv2_w = (const float*)d_in[5];
    const float* bn2_g   = (const float*)d_in[7];
    const float* bn2_b   = (const float*)d_in[8];
    const float* fc1_w   = (const float*)d_in[9];
    const float* bn3_g   = (const float*)d_in[11];
    const float* bn3_b   = (const float*)d_in[12];
    const float* fc2_w   = (const float*)d_in[13];
    const float* fc2_b   = (const float*)d_in[14];
    float* out = (float*)d_out;

    cudaFuncSetAttribute(k_conv2, cudaFuncAttributeMaxDynamicSharedMemorySize, CV2_SMEM_BYTES);

    // quantization (biases dropped: train-mode BN cancels them exactly)
    k_zero_max<<<1, 32>>>();
    k_absmax_all<<<dim3(128, 4), 256>>>(conv1_w, conv2_w, fc1_w, fc2_w);
    k_quant_all <<<dim3(128, 4), 256>>>(conv1_w, conv2_w, fc1_w, fc2_w);

    // stage 1: conv1 + fused raw pool + BN1 stats
    k_conv1<<<dim3(B, C1 / 4), 576>>>(x);
    k_bnfin1<<<C1, 512>>>(bn1_g, bn1_b);

    // stage 2: conv2 (tf32 mma, BN1+ReLU fused at load, raw pool + BN2 partials fused)
    k_conv2<<<B / 2, 256, CV2_SMEM_BYTES>>>();
    k_bnfin2<<<C2, 512>>>(bn2_g, bn2_b);

    // stage 3: fc1 (tf32 mma, BN2+ReLU fused at load), BN3 stats, fc2
    k_fc1<<<dim3(8, 8), 128>>>();
    k_bnstats3<<<16, 256>>>(bn3_g, bn3_b);
    k_fc2<<<B, 320>>>(fc2_b, out);
}

// round 3
// speedup vs baseline: 4.7879x; 1.7524x over previous
#include <cuda_runtime.h>
#include <cuda_bf16.h>

// ---------------- problem constants ----------------
#define B      512
#define C1     64
#define C2     128
#define P1     12
#define FLAT   2048
#define F1     512
#define F2     10
#define BN_EPS 1e-5f

// ---------------- device scratch ----------------
__device__ unsigned g_maxabs[4];
__device__ float g_qw1[C1 * 25];                 // conv1 ternary [oc][25]
__device__ float g_qw2[25 * C2 * C1];            // conv2 ternary [khkw][oc][ci]
__device__ float g_qf1[F1 * FLAT];               // fc1 ternary [f][k]
__device__ float g_qf2[F2 * F1];
__device__ float g_pool1[B * C1 * P1 * P1];      // RAW pooled conv1 (pre-BN)
__device__ float g_p1sum[C1 * B], g_p1sq[C1 * B];
__device__ float g_scale1[C1], g_shift1[C1];
__device__ float g_p2sum[C2 * B], g_p2sq[C2 * B];
__device__ float g_scale2[C2], g_shift2[C2];
__device__ float g_h1[B * FLAT];                 // RAW pooled conv2 (pre-BN), [b][c*16+y*4+x]
__device__ float g_fc1[B * F1];                  // RAW fc1 (pre-BN)
__device__ float g_scale3[F1], g_shift3[F1];

// ---------------- quantization ----------------
__global__ void k_zero_max() {
    if (threadIdx.x < 4) g_maxabs[threadIdx.x] = 0u;
}

__global__ void k_absmax_all(const float* __restrict__ w0, const float* __restrict__ w1,
                             const float* __restrict__ w2, const float* __restrict__ w3) {
    const int slot = blockIdx.y;
    const float* w = (slot == 0) ? w0 : (slot == 1) ? w1 : (slot == 2) ? w2 : w3;
    const int n = (slot == 0) ? 1600 : (slot == 1) ? 204800 : (slot == 2) ? 1048576 : 5120;
    unsigned m = 0u;
    for (int i = blockIdx.x * blockDim.x + threadIdx.x; i < n; i += gridDim.x * blockDim.x)
        m = max(m, __float_as_uint(fabsf(w[i])));
    #pragma unroll
    for (int o = 16; o; o >>= 1)
        m = max(m, __shfl_xor_sync(0xffffffffu, m, o));
    if ((threadIdx.x & 31) == 0) atomicMax(&g_maxabs[slot], m);
}

__global__ void k_quant_all(const float* __restrict__ w0, const float* __restrict__ w1,
                            const float* __restrict__ w2, const float* __restrict__ w3) {
    const int slot = blockIdx.y;
    const float* w = (slot == 0) ? w0 : (slot == 1) ? w1 : (slot == 2) ? w2 : w3;
    const int n = (slot == 0) ? 1600 : (slot == 1) ? 204800 : (slot == 2) ? 1048576 : 5120;
    const float t = 0.05f * __uint_as_float(g_maxabs[slot]);
    for (int i = blockIdx.x * blockDim.x + threadIdx.x; i < n; i += gridDim.x * blockDim.x) {
        float v = w[i];
        float q = (v > t) ? 1.0f : ((v < -t) ? -1.0f : 0.0f);
        if (slot == 0)      g_qw1[i] = q;
        else if (slot == 1) {
            int oc = i / 1600, rem = i % 1600, ci = rem / 25, kk = rem % 25;
            g_qw2[kk * (C2 * C1) + oc * C1 + ci] = q;   // [khkw][oc][ci]
        }
        else if (slot == 2) g_qf1[i] = q;
        else                g_qf2[i] = q;
    }
}

// ---------------- conv1: 4oc x 4px register tile + fused pool + BN1 partials ------------
// grid (512, 4): image x 16-oc group. 576 threads: 4 oc-quads x 144 px-groups (4px each).
__global__ __launch_bounds__(576) void k_conv1(const float* __restrict__ x) {
    __shared__ float sx[784];
    __shared__ float sw[400];
    __shared__ float sconv[16 * 577];
    __shared__ float sp1[16 * 36], sp2[16 * 36];
    const int b = blockIdx.x, og = blockIdx.y * 16, t = threadIdx.x;

    for (int i = t; i < 784; i += 576) sx[i] = x[b * 784 + i];
    for (int i = t; i < 400; i += 576) sw[i] = g_qw1[og * 25 + i];
    __syncthreads();

    const int ocq = t / 144;            // 0..3 -> oc base ocq*4
    const int g   = t % 144;
    const int y   = g / 6, x0 = (g % 6) * 4;
    const int ocb = ocq * 4;

    float acc[4][4];
    #pragma unroll
    for (int j = 0; j < 4; j++)
        #pragma unroll
        for (int i = 0; i < 4; i++) acc[j][i] = 0.f;

    #pragma unroll
    for (int kh = 0; kh < 5; kh++) {
        float w[4][5];
        #pragma unroll
        for (int j = 0; j < 4; j++)
            #pragma unroll
            for (int kw = 0; kw < 5; kw++)
                w[j][kw] = sw[(ocb + j) * 25 + kh * 5 + kw];
        float xv[8];
        #pragma unroll
        for (int i = 0; i < 8; i++) xv[i] = sx[(y + kh) * 28 + x0 + i];
        #pragma unroll
        for (int kw = 0; kw < 5; kw++)
            #pragma unroll
            for (int j = 0; j < 4; j++)
                #pragma unroll
                for (int i = 0; i < 4; i++)
                    acc[j][i] = fmaf(w[j][kw], xv[kw + i], acc[j][i]);
    }

    #pragma unroll
    for (int j = 0; j < 4; j++)
        #pragma unroll
        for (int i = 0; i < 4; i++)
            sconv[(ocb + j) * 577 + y * 24 + x0 + i] = acc[j][i];
    __syncthreads();

    // BN1 partials stage 1: 16 oc x 36 segments of 16
    {
        int oc = t / 36, seg = t % 36;
        const float* p = &sconv[oc * 577 + seg * 16];
        float s = 0.f, q = 0.f;
        #pragma unroll
        for (int i = 0; i < 16; i++) { float v = p[i]; s += v; q += v * v; }
        sp1[oc * 36 + seg] = s; sp2[oc * 36 + seg] = q;
    }
    // raw 2x2 max-pool: 144 positions x 4 oc per thread
    {
        int pos = t % 144, oq = t / 144;
        int py = pos / 12, px = pos % 12;
        #pragma unroll
        for (int j = 0; j < 4; j++) {
            int oc = oq + 4 * j;
            const float* p = &sconv[oc * 577 + (2 * py) * 24 + 2 * px];
            float m = fmaxf(fmaxf(p[0], p[1]), fmaxf(p[24], p[25]));
            g_pool1[(b * C1 + og + oc) * 144 + pos] = m;
        }
    }
    __syncthreads();
    if (t < 16) {
        float s = 0.f, q = 0.f;
        for (int i = 0; i < 36; i++) { s += sp1[t * 36 + i]; q += sp2[t * 36 + i]; }
        g_p1sum[(og + t) * B + b] = s;
        g_p1sq [(og + t) * B + b] = q;
    }
}

// ---------------- BN finalize ----------------
__global__ void k_bnfin1(const float* __restrict__ gamma, const float* __restrict__ beta) {
    __shared__ float s1[512], s2[512];
    const int c = blockIdx.x, t = threadIdx.x;
    s1[t] = g_p1sum[c * B + t];
    s2[t] = g_p1sq [c * B + t];
    __syncthreads();
    for (int s = 256; s > 0; s >>= 1) {
        if (t < s) { s1[t] += s1[t + s]; s2[t] += s2[t + s]; }
        __syncthreads();
    }
    if (t == 0) {
        const float invN = 1.0f / (float)(B * 576);
        float mean = s1[0] * invN;
        float var  = s2[0] * invN - mean * mean;
        float sc = gamma[c] * rsqrtf(var + BN_EPS);
        g_scale1[c] = sc;
        g_shift1[c] = beta[c] - mean * sc;
    }
}

__global__ void k_bnfin2(const float* __restrict__ gamma, const float* __restrict__ beta) {
    __shared__ float s1[512], s2[512];
    const int c = blockIdx.x, t = threadIdx.x;
    s1[t] = g_p2sum[c * B + t];
    s2[t] = g_p2sq [c * B + t];
    __syncthreads();
    for (int s = 256; s > 0; s >>= 1) {
        if (t < s) { s1[t] += s1[t + s]; s2[t] += s2[t + s]; }
        __syncthreads();
    }
    if (t == 0) {
        const float invN = 1.0f / (float)(B * 64);
        float mean = s1[0] * invN;
        float var  = s2[0] * invN - mean * mean;
        float sc = gamma[c] * rsqrtf(var + BN_EPS);
        g_scale2[c] = sc;
        g_shift2[c] = beta[c] - mean * sc;
    }
}

// ---------------- conv2: tf32 mma implicit GEMM, 4 images/block, no sB staging ----------
// Input tile stored channel-major, row stride 152 (conflict-free b-frag loads).
// 256 threads = 8 warps: wm(2) x wn(4); warp = 64 oc x 64 px (one image per wn).
#define CV2_XSTR 152
#define CV2_IMG  (64 * CV2_XSTR)                 // 9728 floats per image
#define CV2_SA_OFF (4 * CV2_IMG)                 // 38912
#define CV2_SMEM_FLOATS (4 * CV2_IMG + 128 * 68) // 38912 + 8704 = 47616
#define CV2_SMEM_BYTES (CV2_SMEM_FLOATS * 4)     // 190464

__global__ __launch_bounds__(256, 1) void k_conv2() {
    extern __shared__ float sm[];
    float* sx = sm;                      // [img][ci][152], BN1+ReLU+tf32 applied
    float* sA = sm + CV2_SA_OFF;         // [oc 128][68]
    const int b4 = blockIdx.x * 4;
    const int t = threadIdx.x;
    const int lane = t & 31, warp = t >> 5;
    const int l4 = lane >> 2, lm4 = lane & 3;
    const int wm = warp >> 2, wn = warp & 3;
    const int m0w = wm * 64;

    // stage 4 images: BN1 affine + ReLU + tf32 round, swizzled stride
    for (int i = t; i < 4 * 9216; i += 256) {
        int img = i / 9216, r = i - img * 9216;
        int ci = r / 144, px = r - ci * 144;
        float v = g_pool1[b4 * 9216 + i];
        v = fmaxf(fmaf(g_scale1[ci], v, g_shift1[ci]), 0.0f);
        unsigned u; asm("cvt.rna.tf32.f32 %0, %1;" : "=r"(u) : "f"(v));
        sx[img * CV2_IMG + ci * CV2_XSTR + px] = __uint_as_float(u);
    }

    float c[4][8][4];
    #pragma unroll
    for (int i = 0; i < 4; i++)
        #pragma unroll
        for (int j = 0; j < 8; j++)
            #pragma unroll
            for (int r = 0; r < 4; r++) c[i][j][r] = 0.f;

    for (int khkw = 0; khkw < 25; khkw++) {
        __syncthreads();
        // stage weights [128 oc][64 ci] vectorized
        {
            const float4* wsrc = (const float4*)(g_qw2 + khkw * (C2 * C1));
            #pragma unroll
            for (int j = 0; j < 8; j++) {
                int idx = t + 256 * j;              // 0..2047 float4s
                int oc = idx >> 4, c4 = idx & 15;
                *(float4*)&sA[oc * 68 + c4 * 4] = wsrc[idx];
            }
        }
        __syncthreads();
        const int kh = khkw / 5, kw = khkw % 5;
        const int boff = wn * CV2_IMG + (kh) * 12 + kw + l4;   // + k*152 + nt*12
        #pragma unroll
        for (int ks = 0; ks < 8; ks++) {
            const int k0 = ks * 8;
            unsigned a[4][4], bf[8][2];
            #pragma unroll
            for (int mt = 0; mt < 4; mt++) {
                const float* ap = sA + (m0w + mt * 16 + l4) * 68 + k0 + lm4;
                a[mt][0] = __float_as_uint(ap[0]);
                a[mt][1] = __float_as_uint(ap[8 * 68]);
                a[mt][2] = __float_as_uint(ap[4]);
                a[mt][3] = __float_as_uint(ap[8 * 68 + 4]);
            }
            const float* bp0 = sx + (k0 + lm4) * CV2_XSTR + boff;
            #pragma unroll
            for (int nt = 0; nt < 8; nt++) {
                bf[nt][0] = __float_as_uint(bp0[nt * 12]);
                bf[nt][1] = __float_as_uint(bp0[4 * CV2_XSTR + nt * 12]);
            }
            #pragma unroll
            for (int mt = 0; mt < 4; mt++)
                #pragma unroll
                for (int nt = 0; nt < 8; nt++)
                    asm volatile(
                        "mma.sync.aligned.m16n8k8.row.col.f32.tf32.tf32.f32 "
                        "{%0,%1,%2,%3},{%4,%5,%6,%7},{%8,%9},{%0,%1,%2,%3};"
                        : "+f"(c[mt][nt][0]), "+f"(c[mt][nt][1]),
                          "+f"(c[mt][nt][2]), "+f"(c[mt][nt][3])
                        : "r"(a[mt][0]), "r"(a[mt][1]), "r"(a[mt][2]), "r"(a[mt][3]),
                          "r"(bf[nt][0]), "r"(bf[nt][1]));
        }
    }

    // epilogue: raw 2x2 pool (nt pairs = y pairs, c0/c1 = adjacent x) + BN2 partials
    const int bimg = b4 + wn;
    #pragma unroll
    for (int mt = 0; mt < 4; mt++) {
        int r0 = m0w + mt * 16 + l4;
        #pragma unroll
        for (int tp = 0; tp < 4; tp++) {
            float pA = fmaxf(fmaxf(c[mt][2*tp][0], c[mt][2*tp][1]),
                             fmaxf(c[mt][2*tp+1][0], c[mt][2*tp+1][1]));
            float pB = fmaxf(fmaxf(c[mt][2*tp][2], c[mt][2*tp][3]),
                             fmaxf(c[mt][2*tp+1][2], c[mt][2*tp+1][3]));
            g_h1[bimg * FLAT + r0 * 16 + tp * 4 + lm4] = pA;
            g_h1[bimg * FLAT + (r0 + 8) * 16 + tp * 4 + lm4] = pB;
        }
        float s0 = 0.f, q0 = 0.f, s1 = 0.f, q1 = 0.f;
        #pragma unroll
        for (int nt = 0; nt < 8; nt++) {
            s0 += c[mt][nt][0] + c[mt][nt][1];
            q0 += c[mt][nt][0]*c[mt][nt][0] + c[mt][nt][1]*c[mt][nt][1];
            s1 += c[mt][nt][2] + c[mt][nt][3];
            q1 += c[mt][nt][2]*c[mt][nt][2] + c[mt][nt][3]*c[mt][nt][3];
        }
        s0 += __shfl_xor_sync(0xffffffffu, s0, 1); s0 += __shfl_xor_sync(0xffffffffu, s0, 2);
        q0 += __shfl_xor_sync(0xffffffffu, q0, 1); q0 += __shfl_xor_sync(0xffffffffu, q0, 2);
        s1 += __shfl_xor_sync(0xffffffffu, s1, 1); s1 += __shfl_xor_sync(0xffffffffu, s1, 2);
        q1 += __shfl_xor_sync(0xffffffffu, q1, 1); q1 += __shfl_xor_sync(0xffffffffu, q1, 2);
        if (lm4 == 0) {
            g_p2sum[r0 * B + bimg] = s0;        g_p2sq[r0 * B + bimg] = q0;
            g_p2sum[(r0 + 8) * B + bimg] = s1;  g_p2sq[(r0 + 8) * B + bimg] = q1;
        }
    }
}

// ---------------- fc1: tf32 mma GEMM, BN2+ReLU fused in A-load ----------------
// grid (8, 8), 256 threads = 8 warps (2M x 4N); block tile 64x64, warp 32x16.
__global__ __launch_bounds__(256) void k_fc1() {
    __shared__ float sA[64 * 36];       // [b_l][k_l]
    __shared__ float sB[32 * 88];       // [k_l][f_l]
    const int t = threadIdx.x;
    const int lane = t & 31, warp = t >> 5;
    const int l4 = lane >> 2, lm4 = lane & 3;
    const int wm = warp >> 2, wn = warp & 3;
    const int b0 = blockIdx.x * 64, f0 = blockIdx.y * 64;
    const int m0w = wm * 32, n0w = wn * 16;

    float c[2][2][4];
    #pragma unroll
    for (int i = 0; i < 2; i++)
        #pragma unroll
        for (int j = 0; j < 2; j++)
            #pragma unroll
            for (int r = 0; r < 4; r++) c[i][j][r] = 0.f;

    for (int kc = 0; kc < 64; kc++) {
        if (kc) __syncthreads();
        #pragma unroll
        for (int j = 0; j < 8; j++) {
            int idx = t + 256 * j;
            int bl = idx >> 5, kl = idx & 31;
            int kg = kc * 32 + kl, cch = kg >> 4;
            float v = g_h1[(b0 + bl) * FLAT + kg];
            v = fmaxf(fmaf(g_scale2[cch], v, g_shift2[cch]), 0.0f);
            unsigned u; asm("cvt.rna.tf32.f32 %0, %1;" : "=r"(u) : "f"(v));
            sA[bl * 36 + kl] = __uint_as_float(u);
        }
        #pragma unroll
        for (int j = 0; j < 8; j++) {
            int idx = t + 256 * j;
            int fl = idx >> 5, kl = idx & 31;
            sB[kl * 88 + fl] = g_qf1[(f0 + fl) * FLAT + kc * 32 + kl];
        }
        __syncthreads();
        #pragma unroll
        for (int ks = 0; ks < 4; ks++) {
            const int k0 = ks * 8;
            unsigned a[2][4], bf[2][2];
            #pragma unroll
            for (int mt = 0; mt < 2; mt++) {
                const float* ap = sA + (m0w + mt * 16 + l4) * 36 + k0 + lm4;
                a[mt][0] = __float_as_uint(ap[0]);
                a[mt][1] = __float_as_uint(ap[8 * 36]);
                a[mt][2] = __float_as_uint(ap[4]);
                a[mt][3] = __float_as_uint(ap[8 * 36 + 4]);
            }
            #pragma unroll
            for (int nt = 0; nt < 2; nt++) {
                const float* bp = sB + (k0 + lm4) * 88 + n0w + nt * 8 + l4;
                bf[nt][0] = __float_as_uint(bp[0]);
                bf[nt][1] = __float_as_uint(bp[4 * 88]);
            }
            #pragma unroll
            for (int mt = 0; mt < 2; mt++)
                #pragma unroll
                for (int nt = 0; nt < 2; nt++)
                    asm volatile(
                        "mma.sync.aligned.m16n8k8.row.col.f32.tf32.tf32.f32 "
                        "{%0,%1,%2,%3},{%4,%5,%6,%7},{%8,%9},{%0,%1,%2,%3};"
                        : "+f"(c[mt][nt][0]), "+f"(c[mt][nt][1]),
                          "+f"(c[mt][nt][2]), "+f"(c[mt][nt][3])
                        : "r"(a[mt][0]), "r"(a[mt][1]), "r"(a[mt][2]), "r"(a[mt][3]),
                          "r"(bf[nt][0]), "r"(bf[nt][1]));
        }
    }
    #pragma unroll
    for (int mt = 0; mt < 2; mt++) {
        int rA = b0 + m0w + mt * 16 + l4;
        #pragma unroll
        for (int nt = 0; nt < 2; nt++) {
            int cc = f0 + n0w + nt * 8 + 2 * lm4;
            *(float2*)&g_fc1[rA * F1 + cc]       = make_float2(c[mt][nt][0], c[mt][nt][1]);
            *(float2*)&g_fc1[(rA + 8) * F1 + cc] = make_float2(c[mt][nt][2], c[mt][nt][3]);
        }
    }
}

// ---------------- bn3 stats ----------------
__global__ void k_bnstats3(const float* __restrict__ gamma, const float* __restrict__ beta) {
    __shared__ float ss[256], sq[256];
    const int t = threadIdx.x;
    const int f = blockIdx.x * 32 + (t & 31);
    const int bo = t >> 5;
    float s = 0.f, q = 0.f;
    for (int b = bo; b < B; b += 8) {
        float v = g_fc1[b * F1 + f];
        s += v; q += v * v;
    }
    ss[t] = s; sq[t] = q;
    __syncthreads();
    if (t < 32) {
        float S = 0.f, Q = 0.f;
        for (int w = 0; w < 8; w++) { S += ss[w * 32 + t]; Q += sq[w * 32 + t]; }
        const float invN = 1.0f / (float)B;
        float mean = S * invN;
        float var  = Q * invN - mean * mean;
        int fg = blockIdx.x * 32 + t;
        float sc = gamma[fg] * rsqrtf(var + BN_EPS);
        g_scale3[fg] = sc;
        g_shift3[fg] = beta[fg] - mean * sc;
    }
}

// ---------------- bn3 + relu + fc2 ----------------
__global__ void k_fc2(const float* __restrict__ fc2_b, float* __restrict__ out) {
    __shared__ float sh[F1];
    const int b = blockIdx.x, t = threadIdx.x;
    for (int i = t; i < F1; i += 320) {
        float v = g_fc1[b * F1 + i];
        sh[i] = fmaxf(fmaf(g_scale3[i], v, g_shift3[i]), 0.0f);
    }
    __syncthreads();
    const int w = t >> 5, lane = t & 31;
    float acc = 0.f;
    for (int f = lane; f < F1; f += 32)
        acc = fmaf(sh[f], g_qf2[w * F1 + f], acc);
    #pragma unroll
    for (int o = 16; o; o >>= 1)
        acc += __shfl_xor_sync(0xffffffffu, acc, o);
    if (lane == 0) out[b * F2 + w] = acc + fc2_b[w];
}

// ---------------- launcher ----------------
extern "C" void kernel_launch(void* const* d_in, const int* in_sizes, int n_in,
                              void* d_out, int out_size) {
    const float* x       = (const float*)d_in[0];
    const float* conv1_w = (const float*)d_in[1];
    const float* bn1_g   = (const float*)d_in[3];
    const float* bn1_b   = (const float*)d_in[4];
    const float* conv2_w = (const float*)d_in[5];
    const float* bn2_g   = (const float*)d_in[7];
    const float* bn2_b   = (const float*)d_in[8];
    const float* fc1_w   = (const float*)d_in[9];
    const float* bn3_g   = (const float*)d_in[11];
    const float* bn3_b   = (const float*)d_in[12];
    const float* fc2_w   = (const float*)d_in[13];
    const float* fc2_b   = (const float*)d_in[14];
    float* out = (float*)d_out;

    cudaFuncSetAttribute(k_conv2, cudaFuncAttributeMaxDynamicSharedMemorySize, CV2_SMEM_BYTES);

    // quantization (conv/fc biases dropped: train-mode BN cancels them exactly)
    k_zero_max<<<1, 32>>>();
    k_absmax_all<<<dim3(128, 4), 256>>>(conv1_w, conv2_w, fc1_w, fc2_w);
    k_quant_all <<<dim3(128, 4), 256>>>(conv1_w, conv2_w, fc1_w, fc2_w);

    // stage 1
    k_conv1<<<dim3(B, 4), 576>>>(x);
    k_bnfin1<<<C1, 512>>>(bn1_g, bn1_b);

    // stage 2
    k_conv2<<<B / 4, 256, CV2_SMEM_BYTES>>>();
    k_bnfin2<<<C2, 512>>>(bn2_g, bn2_b);

    // stage 3
    k_fc1<<<dim3(8, 8), 256>>>();
    k_bnstats3<<<16, 256>>>(bn3_g, bn3_b);
    k_fc2<<<B, 320>>>(fc2_b, out);
}

// round 4
// speedup vs baseline: 6.7735x; 1.4147x over previous
#include <cuda_runtime.h>
#include <cuda_fp16.h>
#include <cuda_bf16.h>

// ---------------- problem constants ----------------
#define B      512
#define C1     64
#define C2     128
#define P1     12
#define FLAT   2048
#define F1     512
#define F2     10
#define BN_EPS 1e-5f

// ---------------- device scratch ----------------
__device__ unsigned g_maxabs[4];
__device__ float  g_qw1[C1 * 25];                 // conv1 ternary [oc][25] fp32
__device__ __half g_qw2h[25 * C2 * C1];           // conv2 ternary [khkw][oc][ci] fp16
__device__ __half g_qf1h[F1 * FLAT];              // fc1 ternary [f][k] fp16
__device__ float  g_qf2[F2 * F1];
__device__ float g_pool1[B * C1 * P1 * P1];       // RAW pooled conv1 (pre-BN)
__device__ float g_p1sum[C1 * B], g_p1sq[C1 * B];
__device__ float g_scale1[C1], g_shift1[C1];
__device__ float g_p2sum[C2 * B], g_p2sq[C2 * B];
__device__ float g_scale2[C2], g_shift2[C2];
__device__ float g_h1[B * FLAT];                  // RAW pooled conv2 (pre-BN)
__device__ float g_fc1[B * F1];                   // RAW fc1 (pre-BN)
__device__ float g_scale3[F1], g_shift3[F1];

// ---------------- quantization ----------------
__global__ void k_zero_max() {
    if (threadIdx.x < 4) g_maxabs[threadIdx.x] = 0u;
}

__global__ void k_absmax_all(const float* __restrict__ w0, const float* __restrict__ w1,
                             const float* __restrict__ w2, const float* __restrict__ w3) {
    const int slot = blockIdx.y;
    const float* w = (slot == 0) ? w0 : (slot == 1) ? w1 : (slot == 2) ? w2 : w3;
    const int n = (slot == 0) ? 1600 : (slot == 1) ? 204800 : (slot == 2) ? 1048576 : 5120;
    unsigned m = 0u;
    for (int i = blockIdx.x * blockDim.x + threadIdx.x; i < n; i += gridDim.x * blockDim.x)
        m = max(m, __float_as_uint(fabsf(w[i])));
    #pragma unroll
    for (int o = 16; o; o >>= 1)
        m = max(m, __shfl_xor_sync(0xffffffffu, m, o));
    if ((threadIdx.x & 31) == 0) atomicMax(&g_maxabs[slot], m);
}

__global__ void k_quant_all(const float* __restrict__ w0, const float* __restrict__ w1,
                            const float* __restrict__ w2, const float* __restrict__ w3) {
    const int slot = blockIdx.y;
    const float* w = (slot == 0) ? w0 : (slot == 1) ? w1 : (slot == 2) ? w2 : w3;
    const int n = (slot == 0) ? 1600 : (slot == 1) ? 204800 : (slot == 2) ? 1048576 : 5120;
    const float t = 0.05f * __uint_as_float(g_maxabs[slot]);
    for (int i = blockIdx.x * blockDim.x + threadIdx.x; i < n; i += gridDim.x * blockDim.x) {
        float v = w[i];
        float q = (v > t) ? 1.0f : ((v < -t) ? -1.0f : 0.0f);
        if (slot == 0)      g_qw1[i] = q;
        else if (slot == 1) {
            int oc = i / 1600, rem = i % 1600, ci = rem / 25, kk = rem % 25;
            g_qw2h[kk * (C2 * C1) + oc * C1 + ci] = __float2half(q);
        }
        else if (slot == 2) g_qf1h[i] = __float2half(q);
        else                g_qf2[i] = q;
    }
}

// ---------------- conv1: pool-aligned 2x2 thread tiles, no smem staging ----------------
// grid (512, 4), 576 threads. thread: ocq = t&3 (4 oc = ocq*4+j), pos = t>>2 (pool pos).
__global__ __launch_bounds__(576, 2) void k_conv1(const float* __restrict__ x) {
    __shared__ float sx[784];
    __shared__ float sw[400];
    __shared__ float sred[2][18][16];
    const int b = blockIdx.x, og = blockIdx.y * 16, t = threadIdx.x;

    for (int i = t; i < 784; i += 576) sx[i] = x[b * 784 + i];
    for (int i = t; i < 400; i += 576) sw[i] = g_qw1[og * 25 + i];
    __syncthreads();

    const int ocq = t & 3, pos = t >> 2;
    const int py = pos / 12, px = pos % 12;
    const int ocb = ocq * 4;
    const int iy = 2 * py, ix = 2 * px;

    float acc[4][4];
    #pragma unroll
    for (int j = 0; j < 4; j++)
        #pragma unroll
        for (int i = 0; i < 4; i++) acc[j][i] = 0.f;

    float r0[6], r1[6];
    #pragma unroll
    for (int i = 0; i < 6; i++) r0[i] = sx[iy * 28 + ix + i];

    #pragma unroll
    for (int kh = 0; kh < 5; kh++) {
        #pragma unroll
        for (int i = 0; i < 6; i++) r1[i] = sx[(iy + kh + 1) * 28 + ix + i];
        float w[4][5];
        #pragma unroll
        for (int j = 0; j < 4; j++)
            #pragma unroll
            for (int kw = 0; kw < 5; kw++)
                w[j][kw] = sw[(ocb + j) * 25 + kh * 5 + kw];
        #pragma unroll
        for (int kw = 0; kw < 5; kw++)
            #pragma unroll
            for (int j = 0; j < 4; j++) {
                acc[j][0] = fmaf(w[j][kw], r0[kw],     acc[j][0]);
                acc[j][1] = fmaf(w[j][kw], r0[kw + 1], acc[j][1]);
                acc[j][2] = fmaf(w[j][kw], r1[kw],     acc[j][2]);
                acc[j][3] = fmaf(w[j][kw], r1[kw + 1], acc[j][3]);
            }
        #pragma unroll
        for (int i = 0; i < 6; i++) r0[i] = r1[i];
    }

    const int wid = t >> 5, lane = t & 31;
    #pragma unroll
    for (int j = 0; j < 4; j++) {
        // raw pooled output
        float m = fmaxf(fmaxf(acc[j][0], acc[j][1]), fmaxf(acc[j][2], acc[j][3]));
        g_pool1[(b * C1 + og + ocb + j) * 144 + pos] = m;
        // BN1 partials (raw conv values)
        float s = acc[j][0] + acc[j][1] + acc[j][2] + acc[j][3];
        float q = acc[j][0]*acc[j][0] + acc[j][1]*acc[j][1]
                + acc[j][2]*acc[j][2] + acc[j][3]*acc[j][3];
        #pragma unroll
        for (int o = 4; o < 32; o <<= 1) {
            s += __shfl_xor_sync(0xffffffffu, s, o);
            q += __shfl_xor_sync(0xffffffffu, q, o);
        }
        if (lane < 4) { sred[0][wid][lane * 4 + j] = s; sred[1][wid][lane * 4 + j] = q; }
    }
    __syncthreads();
    if (t < 16) {
        float s = 0.f, q = 0.f;
        #pragma unroll
        for (int w = 0; w < 18; w++) { s += sred[0][w][t]; q += sred[1][w][t]; }
        g_p1sum[(og + t) * B + b] = s;
        g_p1sq [(og + t) * B + b] = q;
    }
}

// ---------------- BN finalize ----------------
__global__ void k_bnfin1(const float* __restrict__ gamma, const float* __restrict__ beta) {
    __shared__ float s1[512], s2[512];
    const int c = blockIdx.x, t = threadIdx.x;
    s1[t] = g_p1sum[c * B + t];
    s2[t] = g_p1sq [c * B + t];
    __syncthreads();
    for (int s = 256; s > 0; s >>= 1) {
        if (t < s) { s1[t] += s1[t + s]; s2[t] += s2[t + s]; }
        __syncthreads();
    }
    if (t == 0) {
        const float invN = 1.0f / (float)(B * 576);
        float mean = s1[0] * invN;
        float var  = s2[0] * invN - mean * mean;
        float sc = gamma[c] * rsqrtf(var + BN_EPS);
        g_scale1[c] = sc;
        g_shift1[c] = beta[c] - mean * sc;
    }
}

__global__ void k_bnfin2(const float* __restrict__ gamma, const float* __restrict__ beta) {
    __shared__ float s1[512], s2[512];
    const int c = blockIdx.x, t = threadIdx.x;
    s1[t] = g_p2sum[c * B + t];
    s2[t] = g_p2sq [c * B + t];
    __syncthreads();
    for (int s = 256; s > 0; s >>= 1) {
        if (t < s) { s1[t] += s1[t + s]; s2[t] += s2[t + s]; }
        __syncthreads();
    }
    if (t == 0) {
        const float invN = 1.0f / (float)(B * 64);
        float mean = s1[0] * invN;
        float var  = s2[0] * invN - mean * mean;
        float sc = gamma[c] * rsqrtf(var + BN_EPS);
        g_scale2[c] = sc;
        g_shift2[c] = beta[c] - mean * sc;
    }
}

// ---------------- conv2: fp16 m16n8k16 implicit GEMM, 4 images/block -------------------
// Image tile pixel-major half: sx[img][px 144][ci], ci-stride 72 halves (conflict-free).
// 256 threads = 8 warps: wm(2) x wn(4); warp = 64 oc x 64 px (one image per wn).
#define CV2_CSTR 72
#define CV2_IMGH (144 * CV2_CSTR)                 // 10368 halves / image
#define CV2_SA_H (4 * CV2_IMGH)                   // 41472
#define CV2_SMEM_BYTES ((CV2_SA_H + 128 * CV2_CSTR) * 2)   // 101376 B

__global__ __launch_bounds__(256, 1) void k_conv2() {
    extern __shared__ __half smh[];
    __half* sxh = smh;                    // pixel-major activations (BN1+ReLU, fp16)
    __half* sA  = smh + CV2_SA_H;         // weights [oc 128][ci], stride 72 halves
    const int b4 = blockIdx.x * 4;
    const int t = threadIdx.x;
    const int lane = t & 31, warp = t >> 5;
    const int l4 = lane >> 2, lm4 = lane & 3;
    const int wm = warp >> 2, wn = warp & 3;
    const int m0w = wm * 64;

    // stage 4 images: BN1 + ReLU + fp16, channel pair -> half2
    for (int idx = t; idx < 4 * 32 * 144; idx += 256) {
        int img = idx / (32 * 144), r = idx - img * (32 * 144);
        int cp = r / 144, px = r - cp * 144;
        int ci0 = 2 * cp;
        float v0 = g_pool1[((b4 + img) * C1 + ci0) * 144 + px];
        float v1 = g_pool1[((b4 + img) * C1 + ci0 + 1) * 144 + px];
        v0 = fmaxf(fmaf(g_scale1[ci0], v0, g_shift1[ci0]), 0.0f);
        v1 = fmaxf(fmaf(g_scale1[ci0 + 1], v1, g_shift1[ci0 + 1]), 0.0f);
        *(__half2*)&sxh[img * CV2_IMGH + px * CV2_CSTR + ci0] = __floats2half2_rn(v0, v1);
    }

    float c[4][8][4];
    #pragma unroll
    for (int i = 0; i < 4; i++)
        #pragma unroll
        for (int j = 0; j < 8; j++)
            #pragma unroll
            for (int r = 0; r < 4; r++) c[i][j][r] = 0.f;

    for (int khkw = 0; khkw < 25; khkw++) {
        __syncthreads();
        // stage weights [128 oc][64 ci] (uint2 = 4 halves)
        {
            const uint2* wsrc = (const uint2*)(g_qw2h + khkw * (C2 * C1));
            #pragma unroll
            for (int j = 0; j < 8; j++) {
                int idx = t + 256 * j;               // 0..2047
                int oc = idx >> 4, c4 = idx & 15;    // 4-half groups
                *(uint2*)&sA[oc * CV2_CSTR + c4 * 4] = wsrc[idx];
            }
        }
        __syncthreads();
        const int kh = khkw / 5, kw = khkw % 5;
        const __half* bbase = sxh + wn * CV2_IMGH
                            + (kh * 12 + kw + l4) * CV2_CSTR + 2 * lm4;
        #pragma unroll
        for (int ks = 0; ks < 4; ks++) {
            const int k0 = ks * 16;
            unsigned a[4][4], bf[8][2];
            #pragma unroll
            for (int mt = 0; mt < 4; mt++) {
                const __half* ap = sA + (m0w + mt * 16 + l4) * CV2_CSTR + k0 + 2 * lm4;
                a[mt][0] = *(const unsigned*)(ap);
                a[mt][1] = *(const unsigned*)(ap + 8 * CV2_CSTR);
                a[mt][2] = *(const unsigned*)(ap + 8);
                a[mt][3] = *(const unsigned*)(ap + 8 * CV2_CSTR + 8);
            }
            const __half* bp = bbase + k0;
            #pragma unroll
            for (int nt = 0; nt < 8; nt++) {
                bf[nt][0] = *(const unsigned*)(bp + nt * 12 * CV2_CSTR);
                bf[nt][1] = *(const unsigned*)(bp + nt * 12 * CV2_CSTR + 8);
            }
            #pragma unroll
            for (int mt = 0; mt < 4; mt++)
                #pragma unroll
                for (int nt = 0; nt < 8; nt++)
                    asm volatile(
                        "mma.sync.aligned.m16n8k16.row.col.f32.f16.f16.f32 "
                        "{%0,%1,%2,%3},{%4,%5,%6,%7},{%8,%9},{%0,%1,%2,%3};"
                        : "+f"(c[mt][nt][0]), "+f"(c[mt][nt][1]),
                          "+f"(c[mt][nt][2]), "+f"(c[mt][nt][3])
                        : "r"(a[mt][0]), "r"(a[mt][1]), "r"(a[mt][2]), "r"(a[mt][3]),
                          "r"(bf[nt][0]), "r"(bf[nt][1]));
        }
    }

    // epilogue: raw 2x2 pool + BN2 partials (thread-local C layout)
    const int bimg = b4 + wn;
    #pragma unroll
    for (int mt = 0; mt < 4; mt++) {
        int r0 = m0w + mt * 16 + l4;
        #pragma unroll
        for (int tp = 0; tp < 4; tp++) {
            float pA = fmaxf(fmaxf(c[mt][2*tp][0], c[mt][2*tp][1]),
                             fmaxf(c[mt][2*tp+1][0], c[mt][2*tp+1][1]));
            float pB = fmaxf(fmaxf(c[mt][2*tp][2], c[mt][2*tp][3]),
                             fmaxf(c[mt][2*tp+1][2], c[mt][2*tp+1][3]));
            g_h1[bimg * FLAT + r0 * 16 + tp * 4 + lm4] = pA;
            g_h1[bimg * FLAT + (r0 + 8) * 16 + tp * 4 + lm4] = pB;
        }
        float s0 = 0.f, q0 = 0.f, s1 = 0.f, q1 = 0.f;
        #pragma unroll
        for (int nt = 0; nt < 8; nt++) {
            s0 += c[mt][nt][0] + c[mt][nt][1];
            q0 += c[mt][nt][0]*c[mt][nt][0] + c[mt][nt][1]*c[mt][nt][1];
            s1 += c[mt][nt][2] + c[mt][nt][3];
            q1 += c[mt][nt][2]*c[mt][nt][2] + c[mt][nt][3]*c[mt][nt][3];
        }
        s0 += __shfl_xor_sync(0xffffffffu, s0, 1); s0 += __shfl_xor_sync(0xffffffffu, s0, 2);
        q0 += __shfl_xor_sync(0xffffffffu, q0, 1); q0 += __shfl_xor_sync(0xffffffffu, q0, 2);
        s1 += __shfl_xor_sync(0xffffffffu, s1, 1); s1 += __shfl_xor_sync(0xffffffffu, s1, 2);
        q1 += __shfl_xor_sync(0xffffffffu, q1, 1); q1 += __shfl_xor_sync(0xffffffffu, q1, 2);
        if (lm4 == 0) {
            g_p2sum[r0 * B + bimg] = s0;        g_p2sq[r0 * B + bimg] = q0;
            g_p2sum[(r0 + 8) * B + bimg] = s1;  g_p2sq[(r0 + 8) * B + bimg] = q1;
        }
    }
}

// ---------------- fc1: fp16 m16n8k16 GEMM, BN2+ReLU fused in A-load ----------------
// grid (8, 8), 256 threads = 8 warps (2M x 4N); block tile 64x64, warp 32x16.
#define FC1_STR 40   // halves, conflict-free (20 words: 20*l4+lm4 distinct mod 32)
__global__ __launch_bounds__(256) void k_fc1() {
    __shared__ __half sA[64 * FC1_STR];
    __shared__ __half sB[64 * FC1_STR];
    const int t = threadIdx.x;
    const int lane = t & 31, warp = t >> 5;
    const int l4 = lane >> 2, lm4 = lane & 3;
    const int wm = warp >> 2, wn = warp & 3;
    const int b0 = blockIdx.x * 64, f0 = blockIdx.y * 64;
    const int m0w = wm * 32, n0w = wn * 16;

    float c[2][2][4];
    #pragma unroll
    for (int i = 0; i < 2; i++)
        #pragma unroll
        for (int j = 0; j < 2; j++)
            #pragma unroll
            for (int r = 0; r < 4; r++) c[i][j][r] = 0.f;

    for (int kc = 0; kc < 64; kc++) {
        if (kc) __syncthreads();
        #pragma unroll
        for (int j = 0; j < 4; j++) {
            int idx = t + 256 * j;                 // 0..1023, A half2s
            int bl = idx >> 4, kp = idx & 15;
            int kg = kc * 32 + 2 * kp;
            float v0 = g_h1[(b0 + bl) * FLAT + kg];
            float v1 = g_h1[(b0 + bl) * FLAT + kg + 1];
            int c0 = kg >> 4, c1 = (kg + 1) >> 4;
            v0 = fmaxf(fmaf(g_scale2[c0], v0, g_shift2[c0]), 0.0f);
            v1 = fmaxf(fmaf(g_scale2[c1], v1, g_shift2[c1]), 0.0f);
            *(__half2*)&sA[bl * FC1_STR + 2 * kp] = __floats2half2_rn(v0, v1);
        }
        #pragma unroll
        for (int j = 0; j < 4; j++) {
            int idx = t + 256 * j;                 // 0..1023, B half2s
            int fl = idx >> 4, kp = idx & 15;
            *(unsigned*)&sB[fl * FC1_STR + 2 * kp] =
                *(const unsigned*)&g_qf1h[(f0 + fl) * FLAT + kc * 32 + 2 * kp];
        }
        __syncthreads();
        #pragma unroll
        for (int ks = 0; ks < 2; ks++) {
            const int k0 = ks * 16;
            unsigned a[2][4], bf[2][2];
            #pragma unroll
            for (int mt = 0; mt < 2; mt++) {
                const __half* ap = sA + (m0w + mt * 16 + l4) * FC1_STR + k0 + 2 * lm4;
                a[mt][0] = *(const unsigned*)(ap);
                a[mt][1] = *(const unsigned*)(ap + 8 * FC1_STR);
                a[mt][2] = *(const unsigned*)(ap + 8);
                a[mt][3] = *(const unsigned*)(ap + 8 * FC1_STR + 8);
            }
            #pragma unroll
            for (int nt = 0; nt < 2; nt++) {
                const __half* bp = sB + (n0w + nt * 8 + l4) * FC1_STR + k0 + 2 * lm4;
                bf[nt][0] = *(const unsigned*)(bp);
                bf[nt][1] = *(const unsigned*)(bp + 8);
            }
            #pragma unroll
            for (int mt = 0; mt < 2; mt++)
                #pragma unroll
                for (int nt = 0; nt < 2; nt++)
                    asm volatile(
                        "mma.sync.aligned.m16n8k16.row.col.f32.f16.f16.f32 "
                        "{%0,%1,%2,%3},{%4,%5,%6,%7},{%8,%9},{%0,%1,%2,%3};"
                        : "+f"(c[mt][nt][0]), "+f"(c[mt][nt][1]),
                          "+f"(c[mt][nt][2]), "+f"(c[mt][nt][3])
                        : "r"(a[mt][0]), "r"(a[mt][1]), "r"(a[mt][2]), "r"(a[mt][3]),
                          "r"(bf[nt][0]), "r"(bf[nt][1]));
        }
    }
    #pragma unroll
    for (int mt = 0; mt < 2; mt++) {
        int rA = b0 + m0w + mt * 16 + l4;
        #pragma unroll
        for (int nt = 0; nt < 2; nt++) {
            int cc = f0 + n0w + nt * 8 + 2 * lm4;
            *(float2*)&g_fc1[rA * F1 + cc]       = make_float2(c[mt][nt][0], c[mt][nt][1]);
            *(float2*)&g_fc1[(rA + 8) * F1 + cc] = make_float2(c[mt][nt][2], c[mt][nt][3]);
        }
    }
}

// ---------------- bn3 stats ----------------
__global__ void k_bnstats3(const float* __restrict__ gamma, const float* __restrict__ beta) {
    __shared__ float ss[256], sq[256];
    const int t = threadIdx.x;
    const int f = blockIdx.x * 32 + (t & 31);
    const int bo = t >> 5;
    float s = 0.f, q = 0.f;
    for (int b = bo; b < B; b += 8) {
        float v = g_fc1[b * F1 + f];
        s += v; q += v * v;
    }
    ss[t] = s; sq[t] = q;
    __syncthreads();
    if (t < 32) {
        float S = 0.f, Q = 0.f;
        for (int w = 0; w < 8; w++) { S += ss[w * 32 + t]; Q += sq[w * 32 + t]; }
        const float invN = 1.0f / (float)B;
        float mean = S * invN;
        float var  = Q * invN - mean * mean;
        int fg = blockIdx.x * 32 + t;
        float sc = gamma[fg] * rsqrtf(var + BN_EPS);
        g_scale3[fg] = sc;
        g_shift3[fg] = beta[fg] - mean * sc;
    }
}

// ---------------- bn3 + relu + fc2 ----------------
__global__ void k_fc2(const float* __restrict__ fc2_b, float* __restrict__ out) {
    __shared__ float sh[F1];
    const int b = blockIdx.x, t = threadIdx.x;
    for (int i = t; i < F1; i += 320) {
        float v = g_fc1[b * F1 + i];
        sh[i] = fmaxf(fmaf(g_scale3[i], v, g_shift3[i]), 0.0f);
    }
    __syncthreads();
    const int w = t >> 5, lane = t & 31;
    float acc = 0.f;
    for (int f = lane; f < F1; f += 32)
        acc = fmaf(sh[f], g_qf2[w * F1 + f], acc);
    #pragma unroll
    for (int o = 16; o; o >>= 1)
        acc += __shfl_xor_sync(0xffffffffu, acc, o);
    if (lane == 0) out[b * F2 + w] = acc + fc2_b[w];
}

// ---------------- launcher ----------------
extern "C" void kernel_launch(void* const* d_in, const int* in_sizes, int n_in,
                              void* d_out, int out_size) {
    const float* x       = (const float*)d_in[0];
    const float* conv1_w = (const float*)d_in[1];
    const float* bn1_g   = (const float*)d_in[3];
    const float* bn1_b   = (const float*)d_in[4];
    const float* conv2_w = (const float*)d_in[5];
    const float* bn2_g   = (const float*)d_in[7];
    const float* bn2_b   = (const float*)d_in[8];
    const float* fc1_w   = (const float*)d_in[9];
    const float* bn3_g   = (const float*)d_in[11];
    const float* bn3_b   = (const float*)d_in[12];
    const float* fc2_w   = (const float*)d_in[13];
    const float* fc2_b   = (const float*)d_in[14];
    float* out = (float*)d_out;

    cudaFuncSetAttribute(k_conv2, cudaFuncAttributeMaxDynamicSharedMemorySize, CV2_SMEM_BYTES);

    // quantization (conv/fc biases dropped: train-mode BN cancels them exactly)
    k_zero_max<<<1, 32>>>();
    k_absmax_all<<<dim3(128, 4), 256>>>(conv1_w, conv2_w, fc1_w, fc2_w);
    k_quant_all <<<dim3(128, 4), 256>>>(conv1_w, conv2_w, fc1_w, fc2_w);

    // stage 1
    k_conv1<<<dim3(B, 4), 576>>>(x);
    k_bnfin1<<<C1, 512>>>(bn1_g, bn1_b);

    // stage 2
    k_conv2<<<B / 4, 256, CV2_SMEM_BYTES>>>();
    k_bnfin2<<<C2, 512>>>(bn2_g, bn2_b);

    // stage 3
    k_fc1<<<dim3(8, 8), 256>>>();
    k_bnstats3<<<16, 256>>>(bn3_g, bn3_b);
    k_fc2<<<B, 320>>>(fc2_b, out);
}

// round 5
// speedup vs baseline: 8.1524x; 1.2036x over previous
#include <cuda_runtime.h>
#include <cuda_fp16.h>
#include <cuda_bf16.h>

// ---------------- problem constants ----------------
#define B      512
#define C1     64
#define C2     128
#define FLAT   2048
#define F1     512
#define F2     10
#define BN_EPS 1e-5f

// ---------------- device scratch ----------------
__device__ unsigned g_maxabs[4];                  // zero-init; atomicMax idempotent across replays
__device__ __half g_qw1h[C1 * 32];                // conv1 ternary [oc][k pad 32] (k>=25 stays 0)
__device__ __half g_qw2h[25 * C2 * C1];           // conv2 ternary [khkw][oc][ci]
__device__ __half g_qf1h[F1 * FLAT];              // fc1 ternary [f][k]
__device__ float  g_qf2[F2 * F1];
__device__ float g_pool1[B * 144 * C1];           // RAW pooled conv1 (pre-BN), [b][pixel][ci]
__device__ float g_p1sum[C1 * B], g_p1sq[C1 * B];
__device__ float g_scale1[C1], g_shift1[C1];
__device__ float g_p2sum[C2 * B], g_p2sq[C2 * B];
__device__ float g_scale2[C2], g_shift2[C2];
__device__ float g_h1[B * FLAT];                  // RAW pooled conv2 (pre-BN)
__device__ float g_fc1[B * F1];                   // RAW fc1 (pre-BN)
__device__ float g_scale3[F1], g_shift3[F1];

// ---------------- cp.async helpers ----------------
__device__ __forceinline__ void cp16(__half* smem_dst, const __half* gsrc) {
    unsigned s = (unsigned)__cvta_generic_to_shared(smem_dst);
    asm volatile("cp.async.cg.shared.global [%0], [%1], 16;\n" :: "r"(s), "l"(gsrc));
}
#define CP_COMMIT() asm volatile("cp.async.commit_group;\n" ::: "memory")
#define CP_WAIT0()  asm volatile("cp.async.wait_group 0;\n" ::: "memory")

// ---------------- quantization ----------------
__global__ void k_absmax_all(const float* __restrict__ w0, const float* __restrict__ w1,
                             const float* __restrict__ w2, const float* __restrict__ w3) {
    const int slot = blockIdx.y;
    const float* w = (slot == 0) ? w0 : (slot == 1) ? w1 : (slot == 2) ? w2 : w3;
    const int n4 = ((slot == 0) ? 1600 : (slot == 1) ? 204800 : (slot == 2) ? 1048576 : 5120) >> 2;
    const float4* w4 = (const float4*)w;
    unsigned m = 0u;
    for (int i = blockIdx.x * blockDim.x + threadIdx.x; i < n4; i += gridDim.x * blockDim.x) {
        float4 v = w4[i];
        m = max(m, __float_as_uint(fabsf(v.x)));
        m = max(m, __float_as_uint(fabsf(v.y)));
        m = max(m, __float_as_uint(fabsf(v.z)));
        m = max(m, __float_as_uint(fabsf(v.w)));
    }
    #pragma unroll
    for (int o = 16; o; o >>= 1)
        m = max(m, __shfl_xor_sync(0xffffffffu, m, o));
    if ((threadIdx.x & 31) == 0) atomicMax(&g_maxabs[slot], m);
}

__global__ void k_quant_all(const float* __restrict__ w0, const float* __restrict__ w1,
                            const float* __restrict__ w2, const float* __restrict__ w3) {
    const int slot = blockIdx.y;
    const float* w = (slot == 0) ? w0 : (slot == 1) ? w1 : (slot == 2) ? w2 : w3;
    const int n4 = ((slot == 0) ? 1600 : (slot == 1) ? 204800 : (slot == 2) ? 1048576 : 5120) >> 2;
    const float4* w4 = (const float4*)w;
    const float t = 0.05f * __uint_as_float(g_maxabs[slot]);
    for (int i = blockIdx.x * blockDim.x + threadIdx.x; i < n4; i += gridDim.x * blockDim.x) {
        float4 v = w4[i];
        float q0 = (v.x > t) ? 1.0f : ((v.x < -t) ? -1.0f : 0.0f);
        float q1 = (v.y > t) ? 1.0f : ((v.y < -t) ? -1.0f : 0.0f);
        float q2 = (v.z > t) ? 1.0f : ((v.z < -t) ? -1.0f : 0.0f);
        float q3 = (v.w > t) ? 1.0f : ((v.w < -t) ? -1.0f : 0.0f);
        int base = 4 * i;
        if (slot == 0) {
            // [oc][25] -> [oc][32] half, padded region untouched (stays 0)
            float qs[4] = {q0, q1, q2, q3};
            #pragma unroll
            for (int u = 0; u < 4; u++) {
                int idx = base + u, oc = idx / 25, k = idx - oc * 25;
                g_qw1h[oc * 32 + k] = __float2half(qs[u]);
            }
        } else if (slot == 1) {
            float qs[4] = {q0, q1, q2, q3};
            #pragma unroll
            for (int u = 0; u < 4; u++) {
                int idx = base + u;
                int oc = idx / 1600, rem = idx - oc * 1600, ci = rem / 25, kk = rem - ci * 25;
                g_qw2h[kk * (C2 * C1) + oc * C1 + ci] = __float2half(qs[u]);
            }
        } else if (slot == 2) {
            __half2 h01 = __floats2half2_rn(q0, q1);
            __half2 h23 = __floats2half2_rn(q2, q3);
            *(__half2*)&g_qf1h[base]     = h01;
            *(__half2*)&g_qf1h[base + 2] = h23;
        } else {
            *(float4*)&g_qf2[base] = make_float4(q0, q1, q2, q3);
        }
    }
}

// ---------------- conv1: fp16 mma [64oc x 32k] x [32k x 576px], pool-window-major N ------
// grid 512 (1 image), 256 threads = 8 warps; warp covers 72 px (9 n-tiles), all 64 oc.
#define CV1_SMEM_BYTES (3136 + 5120 + 46080)      // sxf + sA + sB = 54336
__global__ __launch_bounds__(256) void k_conv1(const float* __restrict__ x) {
    extern __shared__ char c1sm[];
    float*  sxf = (float*)c1sm;                   // 784 fp32
    __half* sA  = (__half*)(c1sm + 3136);         // [64 oc][40] (k 0..31)
    __half* sB  = (__half*)(c1sm + 3136 + 5120);  // [576 n][40]
    __shared__ float srs[64][9], srq[64][9];
    const int b = blockIdx.x, t = threadIdx.x;
    const int lane = t & 31, warp = t >> 5;
    const int l4 = lane >> 2, lm4 = lane & 3;

    for (int i = t; i < 784; i += 256) sxf[i] = x[b * 784 + i];
    // weights: uint2 = 4 halves, 512 groups
    #pragma unroll
    for (int j = 0; j < 2; j++) {
        int i = t + 256 * j;
        int oc = i >> 3, c4 = i & 7;
        *(uint2*)&sA[oc * 40 + c4 * 4] = *(const uint2*)&g_qw1h[oc * 32 + c4 * 4];
    }
    __syncthreads();

    // im2col: n = 4*window + j(dy,dx); k = kh*5+kw (25, padded to 32)
    {
        const int kp = t & 15, n0 = t >> 4;
        const int k0 = 2 * kp;
        const int kh0 = k0 / 5, kw0 = k0 - 5 * kh0;
        const int kh1 = (k0 + 1) / 5, kw1 = (k0 + 1) - 5 * kh1;
        const bool e0 = (k0 < 25), e1 = (k0 + 1 < 25);
        #pragma unroll 4
        for (int st = 0; st < 36; st++) {
            int n = n0 + 16 * st;
            int w = n >> 2, j = n & 3;
            int py = w / 12, px = w - 12 * py;
            int iy = 2 * py + (j >> 1), ix = 2 * px + (j & 1);
            float v0 = e0 ? sxf[(iy + kh0) * 28 + ix + kw0] : 0.f;
            float v1 = e1 ? sxf[(iy + kh1) * 28 + ix + kw1] : 0.f;
            *(__half2*)&sB[n * 40 + k0] = __floats2half2_rn(v0, v1);
        }
    }
    __syncthreads();

    unsigned a[4][2][4];
    #pragma unroll
    for (int mt = 0; mt < 4; mt++) {
        const __half* ap = sA + (mt * 16 + l4) * 40 + 2 * lm4;
        #pragma unroll
        for (int ks = 0; ks < 2; ks++) {
            a[mt][ks][0] = *(const unsigned*)(ap + 16 * ks);
            a[mt][ks][1] = *(const unsigned*)(ap + 16 * ks + 8 * 40);
            a[mt][ks][2] = *(const unsigned*)(ap + 16 * ks + 8);
            a[mt][ks][3] = *(const unsigned*)(ap + 16 * ks + 8 * 40 + 8);
        }
    }

    float s0a[4] = {0,0,0,0}, s1a[4] = {0,0,0,0};
    float q0a[4] = {0,0,0,0}, q1a[4] = {0,0,0,0};

    #pragma unroll
    for (int nt = 0; nt < 9; nt++) {
        const __half* bp = sB + (warp * 72 + nt * 8 + l4) * 40 + 2 * lm4;
        unsigned bf[2][2];
        #pragma unroll
        for (int ks = 0; ks < 2; ks++) {
            bf[ks][0] = *(const unsigned*)(bp + 16 * ks);
            bf[ks][1] = *(const unsigned*)(bp + 16 * ks + 8);
        }
        float c[4][4];
        #pragma unroll
        for (int mt = 0; mt < 4; mt++) {
            c[mt][0] = c[mt][1] = c[mt][2] = c[mt][3] = 0.f;
            #pragma unroll
            for (int ks = 0; ks < 2; ks++)
                asm volatile(
                    "mma.sync.aligned.m16n8k16.row.col.f32.f16.f16.f32 "
                    "{%0,%1,%2,%3},{%4,%5,%6,%7},{%8,%9},{%0,%1,%2,%3};"
                    : "+f"(c[mt][0]), "+f"(c[mt][1]), "+f"(c[mt][2]), "+f"(c[mt][3])
                    : "r"(a[mt][ks][0]), "r"(a[mt][ks][1]), "r"(a[mt][ks][2]), "r"(a[mt][ks][3]),
                      "r"(bf[ks][0]), "r"(bf[ks][1]));
        }
        const int wdw = warp * 18 + nt * 2 + (lm4 >> 1);
        #pragma unroll
        for (int mt = 0; mt < 4; mt++) {
            // BN1 partials (raw conv outputs)
            s0a[mt] += c[mt][0] + c[mt][1];
            q0a[mt] += c[mt][0]*c[mt][0] + c[mt][1]*c[mt][1];
            s1a[mt] += c[mt][2] + c[mt][3];
            q1a[mt] += c[mt][2]*c[mt][2] + c[mt][3]*c[mt][3];
            // 2x2 pool: this thread has 2 of 4 window elems; partner lm4^1 has the rest
            float m0 = fmaxf(c[mt][0], c[mt][1]);
            float m1 = fmaxf(c[mt][2], c[mt][3]);
            m0 = fmaxf(m0, __shfl_xor_sync(0xffffffffu, m0, 1));
            m1 = fmaxf(m1, __shfl_xor_sync(0xffffffffu, m1, 1));
            if ((lm4 & 1) == 0) {
                int oc = mt * 16 + l4;
                g_pool1[b * 9216 + wdw * 64 + oc]     = m0;
                g_pool1[b * 9216 + wdw * 64 + oc + 8] = m1;
            }
        }
    }

    #pragma unroll
    for (int mt = 0; mt < 4; mt++) {
        float s0 = s0a[mt], q0 = q0a[mt], s1 = s1a[mt], q1 = q1a[mt];
        s0 += __shfl_xor_sync(0xffffffffu, s0, 1); s0 += __shfl_xor_sync(0xffffffffu, s0, 2);
        q0 += __shfl_xor_sync(0xffffffffu, q0, 1); q0 += __shfl_xor_sync(0xffffffffu, q0, 2);
        s1 += __shfl_xor_sync(0xffffffffu, s1, 1); s1 += __shfl_xor_sync(0xffffffffu, s1, 2);
        q1 += __shfl_xor_sync(0xffffffffu, q1, 1); q1 += __shfl_xor_sync(0xffffffffu, q1, 2);
        if (lm4 == 0) {
            srs[mt * 16 + l4][warp] = s0;     srq[mt * 16 + l4][warp] = q0;
            srs[mt * 16 + l4 + 8][warp] = s1; srq[mt * 16 + l4 + 8][warp] = q1;
        }
    }
    __syncthreads();
    if (t < 64) {
        float S = 0.f, Q = 0.f;
        #pragma unroll
        for (int w = 0; w < 8; w++) { S += srs[t][w]; Q += srq[t][w]; }
        g_p1sum[t * B + b] = S;
        g_p1sq [t * B + b] = Q;
    }
}

// ---------------- BN finalize ----------------
__global__ void k_bnfin1(const float* __restrict__ gamma, const float* __restrict__ beta) {
    __shared__ float s1[512], s2[512];
    const int c = blockIdx.x, t = threadIdx.x;
    s1[t] = g_p1sum[c * B + t];
    s2[t] = g_p1sq [c * B + t];
    __syncthreads();
    for (int s = 256; s > 0; s >>= 1) {
        if (t < s) { s1[t] += s1[t + s]; s2[t] += s2[t + s]; }
        __syncthreads();
    }
    if (t == 0) {
        const float invN = 1.0f / (float)(B * 576);
        float mean = s1[0] * invN;
        float var  = s2[0] * invN - mean * mean;
        float sc = gamma[c] * rsqrtf(var + BN_EPS);
        g_scale1[c] = sc;
        g_shift1[c] = beta[c] - mean * sc;
    }
}

__global__ void k_bnfin2(const float* __restrict__ gamma, const float* __restrict__ beta) {
    __shared__ float s1[512], s2[512];
    const int c = blockIdx.x, t = threadIdx.x;
    s1[t] = g_p2sum[c * B + t];
    s2[t] = g_p2sq [c * B + t];
    __syncthreads();
    for (int s = 256; s > 0; s >>= 1) {
        if (t < s) { s1[t] += s1[t + s]; s2[t] += s2[t + s]; }
        __syncthreads();
    }
    if (t == 0) {
        const float invN = 1.0f / (float)(B * 64);
        float mean = s1[0] * invN;
        float var  = s2[0] * invN - mean * mean;
        float sc = gamma[c] * rsqrtf(var + BN_EPS);
        g_scale2[c] = sc;
        g_shift2[c] = beta[c] - mean * sc;
    }
}

// ---------------- conv2: fp16 m16n8k16 implicit GEMM, 4 images/block -------------------
// Image tile pixel-major half: sx[img][px 144][ci], ci-stride 72 halves (conflict-free).
// Double-buffered cp.async weight staging; 1 syncthreads per khkw.
#define CV2_CSTR 72
#define CV2_IMGH (144 * CV2_CSTR)                 // 10368 halves / image
#define CV2_SA_H (4 * CV2_IMGH)                   // 41472
#define CV2_WBUF (C2 * CV2_CSTR)                  // 9216 halves per weight buffer
#define CV2_SMEM_BYTES ((CV2_SA_H + 2 * CV2_WBUF) * 2)   // 119808 B

__global__ __launch_bounds__(256, 1) void k_conv2() {
    extern __shared__ __half smh[];
    __half* sxh = smh;
    __half* sA0 = smh + CV2_SA_H;
    __half* sA1 = sA0 + CV2_WBUF;
    const int b4 = blockIdx.x * 4;
    const int t = threadIdx.x;
    const int lane = t & 31, warp = t >> 5;
    const int l4 = lane >> 2, lm4 = lane & 3;
    const int wm = warp >> 2, wn = warp & 3;
    const int m0w = wm * 64;

    // kick off weight stage for khkw=0
    {
        const __half* wsrc = g_qw2h;
        #pragma unroll
        for (int j = 0; j < 4; j++) {
            int idx = t + 256 * j;                // 16B units
            int oc = idx >> 3, c8 = idx & 7;
            cp16(sA0 + oc * CV2_CSTR + c8 * 8, wsrc + idx * 8);
        }
        CP_COMMIT();
    }

    // stage 4 images: BN1 + ReLU + fp16; pool1 layout [b][px][ci] -> contiguous float2
    for (int idx = t; idx < 4 * 144 * 32; idx += 256) {
        int img = idx / 4608, r = idx - img * 4608;
        int p = r >> 5, cp = r & 31;
        int ci0 = 2 * cp;
        float2 v = *(const float2*)&g_pool1[(b4 + img) * 9216 + p * 64 + ci0];
        float v0 = fmaxf(fmaf(g_scale1[ci0],     v.x, g_shift1[ci0]),     0.0f);
        float v1 = fmaxf(fmaf(g_scale1[ci0 + 1], v.y, g_shift1[ci0 + 1]), 0.0f);
        *(__half2*)&sxh[img * CV2_IMGH + p * CV2_CSTR + ci0] = __floats2half2_rn(v0, v1);
    }

    float c[4][8][4];
    #pragma unroll
    for (int i = 0; i < 4; i++)
        #pragma unroll
        for (int j = 0; j < 8; j++)
            #pragma unroll
            for (int r = 0; r < 4; r++) c[i][j][r] = 0.f;

    for (int khkw = 0; khkw < 25; khkw++) {
        const __half* sA = (khkw & 1) ? sA1 : sA0;
        CP_WAIT0();
        __syncthreads();      // weights for khkw visible; all warps past khkw-1 mma
        if (khkw < 24) {
            __half* dst = (khkw & 1) ? sA0 : sA1;
            const __half* wsrc = g_qw2h + (khkw + 1) * (C2 * C1);
            #pragma unroll
            for (int j = 0; j < 4; j++) {
                int idx = t + 256 * j;
                int oc = idx >> 3, c8 = idx & 7;
                cp16(dst + oc * CV2_CSTR + c8 * 8, wsrc + idx * 8);
            }
            CP_COMMIT();
        }
        const int kh = khkw / 5, kw = khkw - 5 * kh;
        const __half* bbase = sxh + wn * CV2_IMGH
                            + (kh * 12 + kw + l4) * CV2_CSTR + 2 * lm4;
        #pragma unroll
        for (int ks = 0; ks < 4; ks++) {
            const int k0 = ks * 16;
            unsigned a[4][4], bf[8][2];
            #pragma unroll
            for (int mt = 0; mt < 4; mt++) {
                const __half* ap = sA + (m0w + mt * 16 + l4) * CV2_CSTR + k0 + 2 * lm4;
                a[mt][0] = *(const unsigned*)(ap);
                a[mt][1] = *(const unsigned*)(ap + 8 * CV2_CSTR);
                a[mt][2] = *(const unsigned*)(ap + 8);
                a[mt][3] = *(const unsigned*)(ap + 8 * CV2_CSTR + 8);
            }
            const __half* bp = bbase + k0;
            #pragma unroll
            for (int nt = 0; nt < 8; nt++) {
                bf[nt][0] = *(const unsigned*)(bp + nt * 12 * CV2_CSTR);
                bf[nt][1] = *(const unsigned*)(bp + nt * 12 * CV2_CSTR + 8);
            }
            #pragma unroll
            for (int mt = 0; mt < 4; mt++)
                #pragma unroll
                for (int nt = 0; nt < 8; nt++)
                    asm volatile(
                        "mma.sync.aligned.m16n8k16.row.col.f32.f16.f16.f32 "
                        "{%0,%1,%2,%3},{%4,%5,%6,%7},{%8,%9},{%0,%1,%2,%3};"
                        : "+f"(c[mt][nt][0]), "+f"(c[mt][nt][1]),
                          "+f"(c[mt][nt][2]), "+f"(c[mt][nt][3])
                        : "r"(a[mt][0]), "r"(a[mt][1]), "r"(a[mt][2]), "r"(a[mt][3]),
                          "r"(bf[nt][0]), "r"(bf[nt][1]));
        }
    }

    // epilogue: raw 2x2 pool + BN2 partials (thread-local C layout)
    const int bimg = b4 + wn;
    #pragma unroll
    for (int mt = 0; mt < 4; mt++) {
        int r0 = m0w + mt * 16 + l4;
        #pragma unroll
        for (int tp = 0; tp < 4; tp++) {
            float pA = fmaxf(fmaxf(c[mt][2*tp][0], c[mt][2*tp][1]),
                             fmaxf(c[mt][2*tp+1][0], c[mt][2*tp+1][1]));
            float pB = fmaxf(fmaxf(c[mt][2*tp][2], c[mt][2*tp][3]),
                             fmaxf(c[mt][2*tp+1][2], c[mt][2*tp+1][3]));
            g_h1[bimg * FLAT + r0 * 16 + tp * 4 + lm4] = pA;
            g_h1[bimg * FLAT + (r0 + 8) * 16 + tp * 4 + lm4] = pB;
        }
        float s0 = 0.f, q0 = 0.f, s1 = 0.f, q1 = 0.f;
        #pragma unroll
        for (int nt = 0; nt < 8; nt++) {
            s0 += c[mt][nt][0] + c[mt][nt][1];
            q0 += c[mt][nt][0]*c[mt][nt][0] + c[mt][nt][1]*c[mt][nt][1];
            s1 += c[mt][nt][2] + c[mt][nt][3];
            q1 += c[mt][nt][2]*c[mt][nt][2] + c[mt][nt][3]*c[mt][nt][3];
        }
        s0 += __shfl_xor_sync(0xffffffffu, s0, 1); s0 += __shfl_xor_sync(0xffffffffu, s0, 2);
        q0 += __shfl_xor_sync(0xffffffffu, q0, 1); q0 += __shfl_xor_sync(0xffffffffu, q0, 2);
        s1 += __shfl_xor_sync(0xffffffffu, s1, 1); s1 += __shfl_xor_sync(0xffffffffu, s1, 2);
        q1 += __shfl_xor_sync(0xffffffffu, q1, 1); q1 += __shfl_xor_sync(0xffffffffu, q1, 2);
        if (lm4 == 0) {
            g_p2sum[r0 * B + bimg] = s0;        g_p2sq[r0 * B + bimg] = q0;
            g_p2sum[(r0 + 8) * B + bimg] = s1;  g_p2sq[(r0 + 8) * B + bimg] = q1;
        }
    }
}

// ---------------- fc1: fp16 m16n8k16 GEMM, BN2+ReLU fused in A-load ----------------
#define FC1_STR 40
__global__ __launch_bounds__(256) void k_fc1() {
    __shared__ __half sA[64 * FC1_STR];
    __shared__ __half sB[64 * FC1_STR];
    const int t = threadIdx.x;
    const int lane = t & 31, warp = t >> 5;
    const int l4 = lane >> 2, lm4 = lane & 3;
    const int wm = warp >> 2, wn = warp & 3;
    const int b0 = blockIdx.x * 64, f0 = blockIdx.y * 64;
    const int m0w = wm * 32, n0w = wn * 16;

    float c[2][2][4];
    #pragma unroll
    for (int i = 0; i < 2; i++)
        #pragma unroll
        for (int j = 0; j < 2; j++)
            #pragma unroll
            for (int r = 0; r < 4; r++) c[i][j][r] = 0.f;

    for (int kc = 0; kc < 64; kc++) {
        if (kc) __syncthreads();
        #pragma unroll
        for (int j = 0; j < 4; j++) {
            int idx = t + 256 * j;
            int bl = idx >> 4, kp = idx & 15;
            int kg = kc * 32 + 2 * kp;
            float v0 = g_h1[(b0 + bl) * FLAT + kg];
            float v1 = g_h1[(b0 + bl) * FLAT + kg + 1];
            int c0 = kg >> 4, c1 = (kg + 1) >> 4;
            v0 = fmaxf(fmaf(g_scale2[c0], v0, g_shift2[c0]), 0.0f);
            v1 = fmaxf(fmaf(g_scale2[c1], v1, g_shift2[c1]), 0.0f);
            *(__half2*)&sA[bl * FC1_STR + 2 * kp] = __floats2half2_rn(v0, v1);
        }
        #pragma unroll
        for (int j = 0; j < 4; j++) {
            int idx = t + 256 * j;
            int fl = idx >> 4, kp = idx & 15;
            *(unsigned*)&sB[fl * FC1_STR + 2 * kp] =
                *(const unsigned*)&g_qf1h[(f0 + fl) * FLAT + kc * 32 + 2 * kp];
        }
        __syncthreads();
        #pragma unroll
        for (int ks = 0; ks < 2; ks++) {
            const int k0 = ks * 16;
            unsigned a[2][4], bf[2][2];
            #pragma unroll
            for (int mt = 0; mt < 2; mt++) {
                const __half* ap = sA + (m0w + mt * 16 + l4) * FC1_STR + k0 + 2 * lm4;
                a[mt][0] = *(const unsigned*)(ap);
                a[mt][1] = *(const unsigned*)(ap + 8 * FC1_STR);
                a[mt][2] = *(const unsigned*)(ap + 8);
                a[mt][3] = *(const unsigned*)(ap + 8 * FC1_STR + 8);
            }
            #pragma unroll
            for (int nt = 0; nt < 2; nt++) {
                const __half* bp = sB + (n0w + nt * 8 + l4) * FC1_STR + k0 + 2 * lm4;
                bf[nt][0] = *(const unsigned*)(bp);
                bf[nt][1] = *(const unsigned*)(bp + 8);
            }
            #pragma unroll
            for (int mt = 0; mt < 2; mt++)
                #pragma unroll
                for (int nt = 0; nt < 2; nt++)
                    asm volatile(
                        "mma.sync.aligned.m16n8k16.row.col.f32.f16.f16.f32 "
                        "{%0,%1,%2,%3},{%4,%5,%6,%7},{%8,%9},{%0,%1,%2,%3};"
                        : "+f"(c[mt][nt][0]), "+f"(c[mt][nt][1]),
                          "+f"(c[mt][nt][2]), "+f"(c[mt][nt][3])
                        : "r"(a[mt][0]), "r"(a[mt][1]), "r"(a[mt][2]), "r"(a[mt][3]),
                          "r"(bf[nt][0]), "r"(bf[nt][1]));
        }
    }
    #pragma unroll
    for (int mt = 0; mt < 2; mt++) {
        int rA = b0 + m0w + mt * 16 + l4;
        #pragma unroll
        for (int nt = 0; nt < 2; nt++) {
            int cc = f0 + n0w + nt * 8 + 2 * lm4;
            *(float2*)&g_fc1[rA * F1 + cc]       = make_float2(c[mt][nt][0], c[mt][nt][1]);
            *(float2*)&g_fc1[(rA + 8) * F1 + cc] = make_float2(c[mt][nt][2], c[mt][nt][3]);
        }
    }
}

// ---------------- bn3 stats ----------------
__global__ void k_bnstats3(const float* __restrict__ gamma, const float* __restrict__ beta) {
    __shared__ float ss[256], sq[256];
    const int t = threadIdx.x;
    const int f = blockIdx.x * 32 + (t & 31);
    const int bo = t >> 5;
    float s = 0.f, q = 0.f;
    for (int b = bo; b < B; b += 8) {
        float v = g_fc1[b * F1 + f];
        s += v; q += v * v;
    }
    ss[t] = s; sq[t] = q;
    __syncthreads();
    if (t < 32) {
        float S = 0.f, Q = 0.f;
        for (int w = 0; w < 8; w++) { S += ss[w * 32 + t]; Q += sq[w * 32 + t]; }
        const float invN = 1.0f / (float)B;
        float mean = S * invN;
        float var  = Q * invN - mean * mean;
        int fg = blockIdx.x * 32 + t;
        float sc = gamma[fg] * rsqrtf(var + BN_EPS);
        g_scale3[fg] = sc;
        g_shift3[fg] = beta[fg] - mean * sc;
    }
}

// ---------------- bn3 + relu + fc2: 64 blocks x 8 images, weights in smem ----------------
__global__ __launch_bounds__(256) void k_fc2(const float* __restrict__ fc2_b,
                                             float* __restrict__ out) {
    __shared__ float swq[F2 * F1];
    __shared__ float sbias[F2];
    const int t = threadIdx.x;
    for (int i = t; i < F2 * F1; i += 256) swq[i] = g_qf2[i];
    if (t < F2) sbias[t] = fc2_b[t];
    __syncthreads();
    const int warp = t >> 5, lane = t & 31;
    const int b = blockIdx.x * 8 + warp;
    float h[16];
    #pragma unroll
    for (int i = 0; i < 16; i++) {
        int f = lane + 32 * i;
        float v = g_fc1[b * F1 + f];
        h[i] = fmaxf(fmaf(g_scale3[f], v, g_shift3[f]), 0.0f);
    }
    #pragma unroll
    for (int o = 0; o < F2; o++) {
        float acc = 0.f;
        #pragma unroll
        for (int i = 0; i < 16; i++)
            acc = fmaf(h[i], swq[o * F1 + lane + 32 * i], acc);
        #pragma unroll
        for (int s = 16; s; s >>= 1)
            acc += __shfl_xor_sync(0xffffffffu, acc, s);
        if (lane == 0) out[b * F2 + o] = acc + sbias[o];
    }
}

// ---------------- launcher ----------------
extern "C" void kernel_launch(void* const* d_in, const int* in_sizes, int n_in,
                              void* d_out, int out_size) {
    const float* x       = (const float*)d_in[0];
    const float* conv1_w = (const float*)d_in[1];
    const float* bn1_g   = (const float*)d_in[3];
    const float* bn1_b   = (const float*)d_in[4];
    const float* conv2_w = (const float*)d_in[5];
    const float* bn2_g   = (const float*)d_in[7];
    const float* bn2_b   = (const float*)d_in[8];
    const float* fc1_w   = (const float*)d_in[9];
    const float* bn3_g   = (const float*)d_in[11];
    const float* bn3_b   = (const float*)d_in[12];
    const float* fc2_w   = (const float*)d_in[13];
    const float* fc2_b   = (const float*)d_in[14];
    float* out = (float*)d_out;

    cudaFuncSetAttribute(k_conv1, cudaFuncAttributeMaxDynamicSharedMemorySize, CV1_SMEM_BYTES);
    cudaFuncSetAttribute(k_conv2, cudaFuncAttributeMaxDynamicSharedMemorySize, CV2_SMEM_BYTES);

    // quantization (conv/fc biases dropped: train-mode BN cancels them exactly)
    k_absmax_all<<<dim3(64, 4), 256>>>(conv1_w, conv2_w, fc1_w, fc2_w);
    k_quant_all <<<dim3(64, 4), 256>>>(conv1_w, conv2_w, fc1_w, fc2_w);

    // stage 1
    k_conv1<<<B, 256, CV1_SMEM_BYTES>>>(x);
    k_bnfin1<<<C1, 512>>>(bn1_g, bn1_b);

    // stage 2
    k_conv2<<<B / 4, 256, CV2_SMEM_BYTES>>>();
    k_bnfin2<<<C2, 512>>>(bn2_g, bn2_b);

    // stage 3
    k_fc1<<<dim3(8, 8), 256>>>();
    k_bnstats3<<<16, 256>>>(bn3_g, bn3_b);
    k_fc2<<<B / 8, 256>>>(fc2_b, out);
}

// round 6
// speedup vs baseline: 8.8935x; 1.0909x over previous
#include <cuda_runtime.h>
#include <cuda_fp16.h>
#include <cuda_bf16.h>

// ---------------- problem constants ----------------
#define B      512
#define C1     64
#define C2     128
#define FLAT   2048
#define F1     512
#define F2     10
#define BN_EPS 1e-5f

// ---------------- device scratch ----------------
__device__ unsigned g_maxabs[4];                  // zero-init; atomicMax idempotent across replays
__device__ __half g_qw1h[C1 * 32];                // conv1 ternary [oc][k pad 32]
__device__ __half g_qw2h[25 * C2 * C1];           // conv2 ternary [khkw][oc][ci]
__device__ __half g_qf1h[F1 * FLAT];              // fc1 ternary [f][k]
__device__ float  g_qf2[F2 * F1];
__device__ float g_pool1[B * 144 * C1];           // RAW pooled conv1 (pre-BN), [b][pixel][ci]
__device__ float g_p1sum[C1 * B], g_p1sq[C1 * B];
__device__ float g_scale1[C1], g_shift1[C1];
__device__ float g_p2sum[C2 * B], g_p2sq[C2 * B];
__device__ float g_scale2[C2], g_shift2[C2];
__device__ float g_h1[B * FLAT];                  // RAW pooled conv2 (pre-BN)
__device__ float g_fc1[B * F1];                   // RAW fc1 (pre-BN)
__device__ float g_p3s[F1 * 8], g_p3q[F1 * 8];    // BN3 partials: [feature][b-tile]

// ---------------- cp.async helpers ----------------
__device__ __forceinline__ void cp16(__half* smem_dst, const __half* gsrc) {
    unsigned s = (unsigned)__cvta_generic_to_shared(smem_dst);
    asm volatile("cp.async.cg.shared.global [%0], [%1], 16;\n" :: "r"(s), "l"(gsrc));
}
#define CP_COMMIT() asm volatile("cp.async.commit_group;\n" ::: "memory")
#define CP_WAIT0()  asm volatile("cp.async.wait_group 0;\n" ::: "memory")

// ---------------- quantization ----------------
__global__ void k_absmax_all(const float* __restrict__ w0, const float* __restrict__ w1,
                             const float* __restrict__ w2, const float* __restrict__ w3) {
    const int slot = blockIdx.y;
    const float* w = (slot == 0) ? w0 : (slot == 1) ? w1 : (slot == 2) ? w2 : w3;
    const int n4 = ((slot == 0) ? 1600 : (slot == 1) ? 204800 : (slot == 2) ? 1048576 : 5120) >> 2;
    const float4* w4 = (const float4*)w;
    unsigned m = 0u;
    #pragma unroll 4
    for (int i = blockIdx.x * blockDim.x + threadIdx.x; i < n4; i += gridDim.x * blockDim.x) {
        float4 v = w4[i];
        m = max(m, __float_as_uint(fabsf(v.x)));
        m = max(m, __float_as_uint(fabsf(v.y)));
        m = max(m, __float_as_uint(fabsf(v.z)));
        m = max(m, __float_as_uint(fabsf(v.w)));
    }
    #pragma unroll
    for (int o = 16; o; o >>= 1)
        m = max(m, __shfl_xor_sync(0xffffffffu, m, o));
    if ((threadIdx.x & 31) == 0) atomicMax(&g_maxabs[slot], m);
}

__global__ void k_quant_all(const float* __restrict__ w0, const float* __restrict__ w1,
                            const float* __restrict__ w2, const float* __restrict__ w3) {
    const int slot = blockIdx.y;
    const float* w = (slot == 0) ? w0 : (slot == 1) ? w1 : (slot == 2) ? w2 : w3;
    const int n4 = ((slot == 0) ? 1600 : (slot == 1) ? 204800 : (slot == 2) ? 1048576 : 5120) >> 2;
    const float4* w4 = (const float4*)w;
    const float t = 0.05f * __uint_as_float(g_maxabs[slot]);
    #pragma unroll 2
    for (int i = blockIdx.x * blockDim.x + threadIdx.x; i < n4; i += gridDim.x * blockDim.x) {
        float4 v = w4[i];
        float q0 = (v.x > t) ? 1.0f : ((v.x < -t) ? -1.0f : 0.0f);
        float q1 = (v.y > t) ? 1.0f : ((v.y < -t) ? -1.0f : 0.0f);
        float q2 = (v.z > t) ? 1.0f : ((v.z < -t) ? -1.0f : 0.0f);
        float q3 = (v.w > t) ? 1.0f : ((v.w < -t) ? -1.0f : 0.0f);
        int base = 4 * i;
        if (slot == 0) {
            float qs[4] = {q0, q1, q2, q3};
            #pragma unroll
            for (int u = 0; u < 4; u++) {
                int idx = base + u, oc = idx / 25, k = idx - oc * 25;
                g_qw1h[oc * 32 + k] = __float2half(qs[u]);
            }
        } else if (slot == 1) {
            float qs[4] = {q0, q1, q2, q3};
            #pragma unroll
            for (int u = 0; u < 4; u++) {
                int idx = base + u;
                int oc = idx / 1600, rem = idx - oc * 1600, ci = rem / 25, kk = rem - ci * 25;
                g_qw2h[kk * (C2 * C1) + oc * C1 + ci] = __float2half(qs[u]);
            }
        } else if (slot == 2) {
            *(__half2*)&g_qf1h[base]     = __floats2half2_rn(q0, q1);
            *(__half2*)&g_qf1h[base + 2] = __floats2half2_rn(q2, q3);
        } else {
            *(float4*)&g_qf2[base] = make_float4(q0, q1, q2, q3);
        }
    }
}

// ---------------- conv1: fp16 mma, pool-window-major N ------
#define CV1_SMEM_BYTES (3136 + 5120 + 46080)
__global__ __launch_bounds__(256) void k_conv1(const float* __restrict__ x) {
    extern __shared__ char c1sm[];
    float*  sxf = (float*)c1sm;
    __half* sA  = (__half*)(c1sm + 3136);
    __half* sB  = (__half*)(c1sm + 3136 + 5120);
    __shared__ float srs[64][9], srq[64][9];
    const int b = blockIdx.x, t = threadIdx.x;
    const int lane = t & 31, warp = t >> 5;
    const int l4 = lane >> 2, lm4 = lane & 3;

    for (int i = t; i < 784; i += 256) sxf[i] = x[b * 784 + i];
    #pragma unroll
    for (int j = 0; j < 2; j++) {
        int i = t + 256 * j;
        int oc = i >> 3, c4 = i & 7;
        *(uint2*)&sA[oc * 40 + c4 * 4] = *(const uint2*)&g_qw1h[oc * 32 + c4 * 4];
    }
    __syncthreads();

    {
        const int kp = t & 15, n0 = t >> 4;
        const int k0 = 2 * kp;
        const int kh0 = k0 / 5, kw0 = k0 - 5 * kh0;
        const int kh1 = (k0 + 1) / 5, kw1 = (k0 + 1) - 5 * kh1;
        const bool e0 = (k0 < 25), e1 = (k0 + 1 < 25);
        #pragma unroll 4
        for (int st = 0; st < 36; st++) {
            int n = n0 + 16 * st;
            int w = n >> 2, j = n & 3;
            int py = w / 12, px = w - 12 * py;
            int iy = 2 * py + (j >> 1), ix = 2 * px + (j & 1);
            float v0 = e0 ? sxf[(iy + kh0) * 28 + ix + kw0] : 0.f;
            float v1 = e1 ? sxf[(iy + kh1) * 28 + ix + kw1] : 0.f;
            *(__half2*)&sB[n * 40 + k0] = __floats2half2_rn(v0, v1);
        }
    }
    __syncthreads();

    unsigned a[4][2][4];
    #pragma unroll
    for (int mt = 0; mt < 4; mt++) {
        const __half* ap = sA + (mt * 16 + l4) * 40 + 2 * lm4;
        #pragma unroll
        for (int ks = 0; ks < 2; ks++) {
            a[mt][ks][0] = *(const unsigned*)(ap + 16 * ks);
            a[mt][ks][1] = *(const unsigned*)(ap + 16 * ks + 8 * 40);
            a[mt][ks][2] = *(const unsigned*)(ap + 16 * ks + 8);
            a[mt][ks][3] = *(const unsigned*)(ap + 16 * ks + 8 * 40 + 8);
        }
    }

    float s0a[4] = {0,0,0,0}, s1a[4] = {0,0,0,0};
    float q0a[4] = {0,0,0,0}, q1a[4] = {0,0,0,0};

    #pragma unroll
    for (int nt = 0; nt < 9; nt++) {
        const __half* bp = sB + (warp * 72 + nt * 8 + l4) * 40 + 2 * lm4;
        unsigned bf[2][2];
        #pragma unroll
        for (int ks = 0; ks < 2; ks++) {
            bf[ks][0] = *(const unsigned*)(bp + 16 * ks);
            bf[ks][1] = *(const unsigned*)(bp + 16 * ks + 8);
        }
        float c[4][4];
        #pragma unroll
        for (int mt = 0; mt < 4; mt++) {
            c[mt][0] = c[mt][1] = c[mt][2] = c[mt][3] = 0.f;
            #pragma unroll
            for (int ks = 0; ks < 2; ks++)
                asm volatile(
                    "mma.sync.aligned.m16n8k16.row.col.f32.f16.f16.f32 "
                    "{%0,%1,%2,%3},{%4,%5,%6,%7},{%8,%9},{%0,%1,%2,%3};"
                    : "+f"(c[mt][0]), "+f"(c[mt][1]), "+f"(c[mt][2]), "+f"(c[mt][3])
                    : "r"(a[mt][ks][0]), "r"(a[mt][ks][1]), "r"(a[mt][ks][2]), "r"(a[mt][ks][3]),
                      "r"(bf[ks][0]), "r"(bf[ks][1]));
        }
        const int wdw = warp * 18 + nt * 2 + (lm4 >> 1);
        #pragma unroll
        for (int mt = 0; mt < 4; mt++) {
            s0a[mt] += c[mt][0] + c[mt][1];
            q0a[mt] += c[mt][0]*c[mt][0] + c[mt][1]*c[mt][1];
            s1a[mt] += c[mt][2] + c[mt][3];
            q1a[mt] += c[mt][2]*c[mt][2] + c[mt][3]*c[mt][3];
            float m0 = fmaxf(c[mt][0], c[mt][1]);
            float m1 = fmaxf(c[mt][2], c[mt][3]);
            m0 = fmaxf(m0, __shfl_xor_sync(0xffffffffu, m0, 1));
            m1 = fmaxf(m1, __shfl_xor_sync(0xffffffffu, m1, 1));
            if ((lm4 & 1) == 0) {
                int oc = mt * 16 + l4;
                g_pool1[b * 9216 + wdw * 64 + oc]     = m0;
                g_pool1[b * 9216 + wdw * 64 + oc + 8] = m1;
            }
        }
    }

    #pragma unroll
    for (int mt = 0; mt < 4; mt++) {
        float s0 = s0a[mt], q0 = q0a[mt], s1 = s1a[mt], q1 = q1a[mt];
        s0 += __shfl_xor_sync(0xffffffffu, s0, 1); s0 += __shfl_xor_sync(0xffffffffu, s0, 2);
        q0 += __shfl_xor_sync(0xffffffffu, q0, 1); q0 += __shfl_xor_sync(0xffffffffu, q0, 2);
        s1 += __shfl_xor_sync(0xffffffffu, s1, 1); s1 += __shfl_xor_sync(0xffffffffu, s1, 2);
        q1 += __shfl_xor_sync(0xffffffffu, q1, 1); q1 += __shfl_xor_sync(0xffffffffu, q1, 2);
        if (lm4 == 0) {
            srs[mt * 16 + l4][warp] = s0;     srq[mt * 16 + l4][warp] = q0;
            srs[mt * 16 + l4 + 8][warp] = s1; srq[mt * 16 + l4 + 8][warp] = q1;
        }
    }
    __syncthreads();
    if (t < 64) {
        float S = 0.f, Q = 0.f;
        #pragma unroll
        for (int w = 0; w < 8; w++) { S += srs[t][w]; Q += srq[t][w]; }
        g_p1sum[t * B + b] = S;
        g_p1sq [t * B + b] = Q;
    }
}

// ---------------- BN finalize: warp-per-channel, shfl-only ----------------
// grid 8 (bn1) / 16 (bn2), 256 threads = 8 warps = 8 channels per block
__global__ void k_bnfin1(const float* __restrict__ gamma, const float* __restrict__ beta) {
    const int w = threadIdx.x >> 5, lane = threadIdx.x & 31;
    const int c = blockIdx.x * 8 + w;
    const float4* ps = (const float4*)&g_p1sum[c * B];
    const float4* pq = (const float4*)&g_p1sq [c * B];
    float s = 0.f, q = 0.f;
    #pragma unroll
    for (int i = 0; i < 4; i++) {
        float4 v = ps[lane * 4 + i]; s += v.x + v.y + v.z + v.w;
        float4 u = pq[lane * 4 + i]; q += u.x + u.y + u.z + u.w;
    }
    #pragma unroll
    for (int o = 16; o; o >>= 1) {
        s += __shfl_xor_sync(0xffffffffu, s, o);
        q += __shfl_xor_sync(0xffffffffu, q, o);
    }
    if (lane == 0) {
        const float invN = 1.0f / (float)(B * 576);
        float mean = s * invN;
        float var  = q * invN - mean * mean;
        float sc = gamma[c] * rsqrtf(var + BN_EPS);
        g_scale1[c] = sc;
        g_shift1[c] = beta[c] - mean * sc;
    }
}

__global__ void k_bnfin2(const float* __restrict__ gamma, const float* __restrict__ beta) {
    const int w = threadIdx.x >> 5, lane = threadIdx.x & 31;
    const int c = blockIdx.x * 8 + w;
    const float4* ps = (const float4*)&g_p2sum[c * B];
    const float4* pq = (const float4*)&g_p2sq [c * B];
    float s = 0.f, q = 0.f;
    #pragma unroll
    for (int i = 0; i < 4; i++) {
        float4 v = ps[lane * 4 + i]; s += v.x + v.y + v.z + v.w;
        float4 u = pq[lane * 4 + i]; q += u.x + u.y + u.z + u.w;
    }
    #pragma unroll
    for (int o = 16; o; o >>= 1) {
        s += __shfl_xor_sync(0xffffffffu, s, o);
        q += __shfl_xor_sync(0xffffffffu, q, o);
    }
    if (lane == 0) {
        const float invN = 1.0f / (float)(B * 64);
        float mean = s * invN;
        float var  = q * invN - mean * mean;
        float sc = gamma[c] * rsqrtf(var + BN_EPS);
        g_scale2[c] = sc;
        g_shift2[c] = beta[c] - mean * sc;
    }
}

// ---------------- conv2: fp16 m16n8k16 implicit GEMM, 4 images/block -------------------
#define CV2_CSTR 72
#define CV2_IMGH (144 * CV2_CSTR)
#define CV2_SA_H (4 * CV2_IMGH)
#define CV2_WBUF (C2 * CV2_CSTR)
#define CV2_SMEM_BYTES ((CV2_SA_H + 2 * CV2_WBUF) * 2)

__global__ __launch_bounds__(256, 1) void k_conv2() {
    extern __shared__ __half smh[];
    __half* sxh = smh;
    __half* sA0 = smh + CV2_SA_H;
    __half* sA1 = sA0 + CV2_WBUF;
    const int b4 = blockIdx.x * 4;
    const int t = threadIdx.x;
    const int lane = t & 31, warp = t >> 5;
    const int l4 = lane >> 2, lm4 = lane & 3;
    const int wm = warp >> 2, wn = warp & 3;
    const int m0w = wm * 64;

    {
        const __half* wsrc = g_qw2h;
        #pragma unroll
        for (int j = 0; j < 4; j++) {
            int idx = t + 256 * j;
            int oc = idx >> 3, c8 = idx & 7;
            cp16(sA0 + oc * CV2_CSTR + c8 * 8, wsrc + idx * 8);
        }
        CP_COMMIT();
    }

    for (int idx = t; idx < 4 * 144 * 32; idx += 256) {
        int img = idx / 4608, r = idx - img * 4608;
        int p = r >> 5, cp = r & 31;
        int ci0 = 2 * cp;
        float2 v = *(const float2*)&g_pool1[(b4 + img) * 9216 + p * 64 + ci0];
        float v0 = fmaxf(fmaf(g_scale1[ci0],     v.x, g_shift1[ci0]),     0.0f);
        float v1 = fmaxf(fmaf(g_scale1[ci0 + 1], v.y, g_shift1[ci0 + 1]), 0.0f);
        *(__half2*)&sxh[img * CV2_IMGH + p * CV2_CSTR + ci0] = __floats2half2_rn(v0, v1);
    }

    float c[4][8][4];
    #pragma unroll
    for (int i = 0; i < 4; i++)
        #pragma unroll
        for (int j = 0; j < 8; j++)
            #pragma unroll
            for (int r = 0; r < 4; r++) c[i][j][r] = 0.f;

    for (int khkw = 0; khkw < 25; khkw++) {
        const __half* sA = (khkw & 1) ? sA1 : sA0;
        CP_WAIT0();
        __syncthreads();
        if (khkw < 24) {
            __half* dst = (khkw & 1) ? sA0 : sA1;
            const __half* wsrc = g_qw2h + (khkw + 1) * (C2 * C1);
            #pragma unroll
            for (int j = 0; j < 4; j++) {
                int idx = t + 256 * j;
                int oc = idx >> 3, c8 = idx & 7;
                cp16(dst + oc * CV2_CSTR + c8 * 8, wsrc + idx * 8);
            }
            CP_COMMIT();
        }
        const int kh = khkw / 5, kw = khkw - 5 * kh;
        const __half* bbase = sxh + wn * CV2_IMGH
                            + (kh * 12 + kw + l4) * CV2_CSTR + 2 * lm4;
        #pragma unroll
        for (int ks = 0; ks < 4; ks++) {
            const int k0 = ks * 16;
            unsigned a[4][4], bf[8][2];
            #pragma unroll
            for (int mt = 0; mt < 4; mt++) {
                const __half* ap = sA + (m0w + mt * 16 + l4) * CV2_CSTR + k0 + 2 * lm4;
                a[mt][0] = *(const unsigned*)(ap);
                a[mt][1] = *(const unsigned*)(ap + 8 * CV2_CSTR);
                a[mt][2] = *(const unsigned*)(ap + 8);
                a[mt][3] = *(const unsigned*)(ap + 8 * CV2_CSTR + 8);
            }
            const __half* bp = bbase + k0;
            #pragma unroll
            for (int nt = 0; nt < 8; nt++) {
                bf[nt][0] = *(const unsigned*)(bp + nt * 12 * CV2_CSTR);
                bf[nt][1] = *(const unsigned*)(bp + nt * 12 * CV2_CSTR + 8);
            }
            #pragma unroll
            for (int mt = 0; mt < 4; mt++)
                #pragma unroll
                for (int nt = 0; nt < 8; nt++)
                    asm volatile(
                        "mma.sync.aligned.m16n8k16.row.col.f32.f16.f16.f32 "
                        "{%0,%1,%2,%3},{%4,%5,%6,%7},{%8,%9},{%0,%1,%2,%3};"
                        : "+f"(c[mt][nt][0]), "+f"(c[mt][nt][1]),
                          "+f"(c[mt][nt][2]), "+f"(c[mt][nt][3])
                        : "r"(a[mt][0]), "r"(a[mt][1]), "r"(a[mt][2]), "r"(a[mt][3]),
                          "r"(bf[nt][0]), "r"(bf[nt][1]));
        }
    }

    const int bimg = b4 + wn;
    #pragma unroll
    for (int mt = 0; mt < 4; mt++) {
        int r0 = m0w + mt * 16 + l4;
        #pragma unroll
        for (int tp = 0; tp < 4; tp++) {
            float pA = fmaxf(fmaxf(c[mt][2*tp][0], c[mt][2*tp][1]),
                             fmaxf(c[mt][2*tp+1][0], c[mt][2*tp+1][1]));
            float pB = fmaxf(fmaxf(c[mt][2*tp][2], c[mt][2*tp][3]),
                             fmaxf(c[mt][2*tp+1][2], c[mt][2*tp+1][3]));
            g_h1[bimg * FLAT + r0 * 16 + tp * 4 + lm4] = pA;
            g_h1[bimg * FLAT + (r0 + 8) * 16 + tp * 4 + lm4] = pB;
        }
        float s0 = 0.f, q0 = 0.f, s1 = 0.f, q1 = 0.f;
        #pragma unroll
        for (int nt = 0; nt < 8; nt++) {
            s0 += c[mt][nt][0] + c[mt][nt][1];
            q0 += c[mt][nt][0]*c[mt][nt][0] + c[mt][nt][1]*c[mt][nt][1];
            s1 += c[mt][nt][2] + c[mt][nt][3];
            q1 += c[mt][nt][2]*c[mt][nt][2] + c[mt][nt][3]*c[mt][nt][3];
        }
        s0 += __shfl_xor_sync(0xffffffffu, s0, 1); s0 += __shfl_xor_sync(0xffffffffu, s0, 2);
        q0 += __shfl_xor_sync(0xffffffffu, q0, 1); q0 += __shfl_xor_sync(0xffffffffu, q0, 2);
        s1 += __shfl_xor_sync(0xffffffffu, s1, 1); s1 += __shfl_xor_sync(0xffffffffu, s1, 2);
        q1 += __shfl_xor_sync(0xffffffffu, q1, 1); q1 += __shfl_xor_sync(0xffffffffu, q1, 2);
        if (lm4 == 0) {
            g_p2sum[r0 * B + bimg] = s0;        g_p2sq[r0 * B + bimg] = q0;
            g_p2sum[(r0 + 8) * B + bimg] = s1;  g_p2sq[(r0 + 8) * B + bimg] = q1;
        }
    }
}

// ---------------- fc1: fp16 mma, k-chunk 128, BN2+ReLU fused, BN3 partials in epilogue --
#define FC1_STR 136
__global__ __launch_bounds__(256) void k_fc1() {
    __shared__ __half sA[64 * FC1_STR];
    __shared__ __half sB[64 * FC1_STR];
    const int t = threadIdx.x;
    const int lane = t & 31, warp = t >> 5;
    const int l4 = lane >> 2, lm4 = lane & 3;
    const int wm = warp >> 2, wn = warp & 3;
    const int b0 = blockIdx.x * 64, f0 = blockIdx.y * 64;
    const int m0w = wm * 32, n0w = wn * 16;

    float c[2][2][4];
    #pragma unroll
    for (int i = 0; i < 2; i++)
        #pragma unroll
        for (int j = 0; j < 2; j++)
            #pragma unroll
            for (int r = 0; r < 4; r++) c[i][j][r] = 0.f;

    for (int kc = 0; kc < 16; kc++) {
        if (kc) __syncthreads();
        // A: 64 rows x 128 k halves (BN2+ReLU from fp32 g_h1)
        #pragma unroll
        for (int j = 0; j < 16; j++) {
            int idx = t + 256 * j;                 // 0..4095 half2
            int bl = idx >> 6, kp = idx & 63;
            int kg = kc * 128 + 2 * kp;
            float2 v = *(const float2*)&g_h1[(b0 + bl) * FLAT + kg];
            int c0 = kg >> 4, c1 = (kg + 1) >> 4;
            float v0 = fmaxf(fmaf(g_scale2[c0], v.x, g_shift2[c0]), 0.0f);
            float v1 = fmaxf(fmaf(g_scale2[c1], v.y, g_shift2[c1]), 0.0f);
            *(__half2*)&sA[bl * FC1_STR + 2 * kp] = __floats2half2_rn(v0, v1);
        }
        // B: 64 f x 128 k halves, 16B vector loads
        #pragma unroll
        for (int j = 0; j < 4; j++) {
            int idx = t + 256 * j;                 // 0..1023 uint4
            int fl = idx >> 4, k8 = idx & 15;
            *(uint4*)&sB[fl * FC1_STR + k8 * 8] =
                *(const uint4*)&g_qf1h[(f0 + fl) * FLAT + kc * 128 + k8 * 8];
        }
        __syncthreads();
        #pragma unroll
        for (int ks = 0; ks < 8; ks++) {
            const int k0 = ks * 16;
            unsigned a[2][4], bf[2][2];
            #pragma unroll
            for (int mt = 0; mt < 2; mt++) {
                const __half* ap = sA + (m0w + mt * 16 + l4) * FC1_STR + k0 + 2 * lm4;
                a[mt][0] = *(const unsigned*)(ap);
                a[mt][1] = *(const unsigned*)(ap + 8 * FC1_STR);
                a[mt][2] = *(const unsigned*)(ap + 8);
                a[mt][3] = *(const unsigned*)(ap + 8 * FC1_STR + 8);
            }
            #pragma unroll
            for (int nt = 0; nt < 2; nt++) {
                const __half* bp = sB + (n0w + nt * 8 + l4) * FC1_STR + k0 + 2 * lm4;
                bf[nt][0] = *(const unsigned*)(bp);
                bf[nt][1] = *(const unsigned*)(bp + 8);
            }
            #pragma unroll
            for (int mt = 0; mt < 2; mt++)
                #pragma unroll
                for (int nt = 0; nt < 2; nt++)
                    asm volatile(
                        "mma.sync.aligned.m16n8k16.row.col.f32.f16.f16.f32 "
                        "{%0,%1,%2,%3},{%4,%5,%6,%7},{%8,%9},{%0,%1,%2,%3};"
                        : "+f"(c[mt][nt][0]), "+f"(c[mt][nt][1]),
                          "+f"(c[mt][nt][2]), "+f"(c[mt][nt][3])
                        : "r"(a[mt][0]), "r"(a[mt][1]), "r"(a[mt][2]), "r"(a[mt][3]),
                          "r"(bf[nt][0]), "r"(bf[nt][1]));
        }
    }
    // write raw fc1
    #pragma unroll
    for (int mt = 0; mt < 2; mt++) {
        int rA = b0 + m0w + mt * 16 + l4;
        #pragma unroll
        for (int nt = 0; nt < 2; nt++) {
            int cc = f0 + n0w + nt * 8 + 2 * lm4;
            *(float2*)&g_fc1[rA * F1 + cc]       = make_float2(c[mt][nt][0], c[mt][nt][1]);
            *(float2*)&g_fc1[(rA + 8) * F1 + cc] = make_float2(c[mt][nt][2], c[mt][nt][3]);
        }
    }
    // BN3 partials: per-feature sum/sumsq over this block's 64 batch rows
    __syncthreads();                    // everyone done reading sB
    float* srs = (float*)sB;            // [2 wm][64 f]
    float* srq = srs + 128;
    #pragma unroll
    for (int nt = 0; nt < 2; nt++) {
        #pragma unroll
        for (int j = 0; j < 2; j++) {
            float s = 0.f, q = 0.f;
            #pragma unroll
            for (int mt = 0; mt < 2; mt++) {
                s += c[mt][nt][j] + c[mt][nt][j + 2];
                q += c[mt][nt][j]*c[mt][nt][j] + c[mt][nt][j+2]*c[mt][nt][j+2];
            }
            #pragma unroll
            for (int o = 4; o < 32; o <<= 1) {
                s += __shfl_xor_sync(0xffffffffu, s, o);
                q += __shfl_xor_sync(0xffffffffu, q, o);
            }
            if (l4 == 0) {
                int fl = n0w + nt * 8 + 2 * lm4 + j;
                srs[wm * 64 + fl] = s;
                srq[wm * 64 + fl] = q;
            }
        }
    }
    __syncthreads();
    if (t < 64) {
        float S = srs[t] + srs[64 + t];
        float Q = srq[t] + srq[64 + t];
        g_p3s[(f0 + t) * 8 + blockIdx.x] = S;
        g_p3q[(f0 + t) * 8 + blockIdx.x] = Q;
    }
}

// ---------------- fc2: BN3 finalize (redundant per block) + bn3+relu+fc2 ----------------
__global__ __launch_bounds__(256) void k_fc2(const float* __restrict__ fc2_b,
                                             const float* __restrict__ bn3_g,
                                             const float* __restrict__ bn3_b,
                                             float* __restrict__ out) {
    __shared__ float swq[F2 * F1];
    __shared__ float sscale[F1], sshift[F1];
    __shared__ float sbias[F2];
    const int t = threadIdx.x;
    for (int i = t; i < F2 * F1; i += 256) swq[i] = g_qf2[i];
    if (t < F2) sbias[t] = fc2_b[t];
    #pragma unroll
    for (int j = 0; j < 2; j++) {
        int f = t + 256 * j;
        float4 sa = *(const float4*)&g_p3s[f * 8];
        float4 sb = *(const float4*)&g_p3s[f * 8 + 4];
        float4 qa = *(const float4*)&g_p3q[f * 8];
        float4 qb = *(const float4*)&g_p3q[f * 8 + 4];
        float S = sa.x + sa.y + sa.z + sa.w + sb.x + sb.y + sb.z + sb.w;
        float Q = qa.x + qa.y + qa.z + qa.w + qb.x + qb.y + qb.z + qb.w;
        const float invN = 1.0f / (float)B;
        float mean = S * invN;
        float var  = Q * invN - mean * mean;
        float sc = bn3_g[f] * rsqrtf(var + BN_EPS);
        sscale[f] = sc;
        sshift[f] = bn3_b[f] - mean * sc;
    }
    __syncthreads();
    const int warp = t >> 5, lane = t & 31;
    const int b = blockIdx.x * 8 + warp;
    float h[16];
    #pragma unroll
    for (int i = 0; i < 16; i++) {
        int f = lane + 32 * i;
        float v = g_fc1[b * F1 + f];
        h[i] = fmaxf(fmaf(sscale[f], v, sshift[f]), 0.0f);
    }
    #pragma unroll
    for (int o = 0; o < F2; o++) {
        float acc = 0.f;
        #pragma unroll
        for (int i = 0; i < 16; i++)
            acc = fmaf(h[i], swq[o * F1 + lane + 32 * i], acc);
        #pragma unroll
        for (int s = 16; s; s >>= 1)
            acc += __shfl_xor_sync(0xffffffffu, acc, s);
        if (lane == 0) out[b * F2 + o] = acc + sbias[o];
    }
}

// ---------------- launcher ----------------
extern "C" void kernel_launch(void* const* d_in, const int* in_sizes, int n_in,
                              void* d_out, int out_size) {
    const float* x       = (const float*)d_in[0];
    const float* conv1_w = (const float*)d_in[1];
    const float* bn1_g   = (const float*)d_in[3];
    const float* bn1_b   = (const float*)d_in[4];
    const float* conv2_w = (const float*)d_in[5];
    const float* bn2_g   = (const float*)d_in[7];
    const float* bn2_b   = (const float*)d_in[8];
    const float* fc1_w   = (const float*)d_in[9];
    const float* bn3_g   = (const float*)d_in[11];
    const float* bn3_b   = (const float*)d_in[12];
    const float* fc2_w   = (const float*)d_in[13];
    const float* fc2_b   = (const float*)d_in[14];
    float* out = (float*)d_out;

    cudaFuncSetAttribute(k_conv1, cudaFuncAttributeMaxDynamicSharedMemorySize, CV1_SMEM_BYTES);
    cudaFuncSetAttribute(k_conv2, cudaFuncAttributeMaxDynamicSharedMemorySize, CV2_SMEM_BYTES);

    // quantization (conv/fc biases dropped: train-mode BN cancels them exactly)
    k_absmax_all<<<dim3(128, 4), 256>>>(conv1_w, conv2_w, fc1_w, fc2_w);
    k_quant_all <<<dim3(128, 4), 256>>>(conv1_w, conv2_w, fc1_w, fc2_w);

    // stage 1
    k_conv1<<<B, 256, CV1_SMEM_BYTES>>>(x);
    k_bnfin1<<<8, 256>>>(bn1_g, bn1_b);

    // stage 2
    k_conv2<<<B / 4, 256, CV2_SMEM_BYTES>>>();
    k_bnfin2<<<16, 256>>>(bn2_g, bn2_b);

    // stage 3 (BN3 stats produced by fc1 epilogue; finalized inside fc2)
    k_fc1<<<dim3(8, 8), 256>>>();
    k_fc2<<<B / 8, 256>>>(fc2_b, bn3_g, bn3_b, out);
}